// round 10
// baseline (speedup 1.0000x reference)
#include <cuda_runtime.h>
#include <math.h>
#include <stdint.h>

#define BB 2
#define SS 2048
#define DD 1024
#define HH 16
#define HD 64

// Single dynamic-smem declaration shared by all kernels.
extern __shared__ char dynsmem[];

// Scratch: projected Q,K in [B,H,S,HD]; V transposed in [B,H,HD,S]
__device__ float g_Q[BB * HH * SS * HD];
__device__ float g_K[BB * HH * SS * HD];
__device__ float g_V[BB * HH * SS * HD];   // [B,H,HD,S] layout!
__device__ int g_klen[BB];
__device__ int g_qlen[BB];

// ---------------------------------------------------------------------------
// helpers
// ---------------------------------------------------------------------------
__device__ __forceinline__ uint32_t smem_u32(const void* p) {
    uint32_t a;
    asm("{ .reg .u64 t; cvta.to.shared.u64 t, %1; cvt.u32.u64 %0, t; }" : "=r"(a) : "l"(p));
    return a;
}
#define SWZ128(x) ((x) ^ (((x) >> 3) & 0x70))

__device__ __forceinline__ void cp16(uint32_t dst, const void* src) {
    asm volatile("cp.async.cg.shared.global [%0], [%1], 16;" :: "r"(dst), "l"(src) : "memory");
}
#define CP_COMMIT() asm volatile("cp.async.commit_group;" ::: "memory")
#define CP_WAIT0() asm volatile("cp.async.wait_group 0;" ::: "memory")
#define CP_WAIT1() asm volatile("cp.async.wait_group 1;" ::: "memory")

__device__ __forceinline__ unsigned tf32u(float x) {
    unsigned u; asm("cvt.rna.tf32.f32 %0, %1;" : "=r"(u) : "f"(x)); return u;
}
__device__ __forceinline__ float tf32f(float x) {
    return __uint_as_float(tf32u(x));
}
__device__ __forceinline__ void mma8(float& c0, float& c1, float& c2, float& c3,
                                     unsigned a0, unsigned a1, unsigned a2, unsigned a3,
                                     unsigned b0, unsigned b1) {
    asm volatile(
        "mma.sync.aligned.m16n8k8.row.col.f32.tf32.tf32.f32 "
        "{%0,%1,%2,%3},{%4,%5,%6,%7},{%8,%9},{%0,%1,%2,%3};"
        : "+f"(c0), "+f"(c1), "+f"(c2), "+f"(c3)
        : "r"(a0), "r"(a1), "r"(a2), "r"(a3), "r"(b0), "r"(b1));
}

// ---------------------------------------------------------------------------
// Projection GEMM, tf32 mma.sync. BM=128, BN=128 (2 heads), BK=32.
// 8 warps in 4(m)x2(n); warp tile 32x64. 2-stage cp.async double buffer.
// CTA (0,0,0) additionally computes the mask lengths (folds len_kernel).
// blockIdx.z selects projection: 0->g_Q, 1->g_K, 2->g_V ([B,H,HD,S]).
// ---------------------------------------------------------------------------
#define PSTAGE 32768         // A 16KB + B 16KB
#define PB_OFF 16384
#define PROJ_SMEM (2 * PSTAGE)

__global__ __launch_bounds__(256, 2) void proj_kernel(
    const float* __restrict__ q, const float* __restrict__ k, const float* __restrict__ v,
    const float* __restrict__ Wq, const float* __restrict__ Wk, const float* __restrict__ Wv,
    const float* __restrict__ bq, const float* __restrict__ bk, const float* __restrict__ bv,
    const unsigned char* __restrict__ km, const unsigned char* __restrict__ qm) {
    char* smem = dynsmem;
    const uint32_t sb = smem_u32(smem);
    const int tid = threadIdx.x;
    const int lane = tid & 31;
    const int wid = tid >> 5;
    const int g = lane >> 2;
    const int t = lane & 3;
    const int wy = wid & 3;    // m band (32 rows)
    const int wx = wid >> 2;   // n half (64 cols)

    // --- fold mask-length computation into one CTA (hidden in the wave) ---
    __shared__ int cnt[4];     // klen[0], klen[1], qlen[0], qlen[1]
    if (blockIdx.x == 0 && blockIdx.y == 0 && blockIdx.z == 0) {
        if (tid < 4) cnt[tid] = 0;
        __syncthreads();
        int wk = (km[1] | km[2] | km[3]) ? 1 : 4;
        int wq = (qm[1] | qm[2] | qm[3]) ? 1 : 4;
#pragma unroll
        for (int b = 0; b < BB; b++) {
            int ck = 0, cq = 0;
            for (int i = tid; i < SS * wk; i += 256) ck += (km[(size_t)b * SS * wk + i] != 0);
            for (int i = tid; i < SS * wq; i += 256) cq += (qm[(size_t)b * SS * wq + i] != 0);
#pragma unroll
            for (int o = 16; o > 0; o >>= 1) {
                ck += __shfl_down_sync(0xffffffffu, ck, o);
                cq += __shfl_down_sync(0xffffffffu, cq, o);
            }
            if (lane == 0) { atomicAdd(&cnt[b], ck); atomicAdd(&cnt[2 + b], cq); }
        }
        __syncthreads();
        if (tid < 2) { g_klen[tid] = cnt[tid]; g_qlen[tid] = cnt[2 + tid]; }
    }

    const int which = blockIdx.z;
    const float* X = (which == 0) ? q : (which == 1) ? k : v;
    const float* W = (which == 0) ? Wq : (which == 1) ? Wk : Wv;
    const float* bias = (which == 0) ? bq : (which == 1) ? bk : bv;
    float* dst = (which == 0) ? g_Q : (which == 1) ? g_K : g_V;

    const int n0 = blockIdx.x * 128;
    const int m0 = blockIdx.y * 128;

    const int r0 = tid >> 3;         // 0..31, +32 per i
    const int cb = (tid & 7) * 16;   // byte col of 16B chunk in 128B row

    float acc[2][8][4] = {};

    auto load_tile = [&](int kt, int stage) {
        const int kf = kt * 32 + (cb >> 2);
        const uint32_t abase = sb + stage * PSTAGE;
#pragma unroll
        for (int i = 0; i < 4; i++) {
            int r = r0 + 32 * i;
            uint32_t sw = SWZ128((uint32_t)(r * 128 + cb));
            cp16(abase + sw, X + (size_t)(m0 + r) * DD + kf);
            cp16(abase + PB_OFF + sw, W + (size_t)(n0 + r) * DD + kf);
        }
    };

    load_tile(0, 0); CP_COMMIT();
    load_tile(1, 1); CP_COMMIT();

    for (int kt = 0; kt < 32; kt++) {
        const int st = kt & 1;
        if (kt < 30) CP_WAIT1(); else CP_WAIT0();
        __syncthreads();

        const char* A = smem + st * PSTAGE;
        const char* Bm = A + PB_OFF;
#pragma unroll
        for (int ks = 0; ks < 4; ks++) {
            const int kc = ks * 8;
            unsigned a[2][4];
#pragma unroll
            for (int mi = 0; mi < 2; mi++) {
                int r = wy * 32 + mi * 16;
                a[mi][0] = __float_as_uint(*(const float*)(A + SWZ128((uint32_t)((r + g) * 128 + (kc + t) * 4))));
                a[mi][1] = __float_as_uint(*(const float*)(A + SWZ128((uint32_t)((r + 8 + g) * 128 + (kc + t) * 4))));
                a[mi][2] = __float_as_uint(*(const float*)(A + SWZ128((uint32_t)((r + g) * 128 + (kc + t + 4) * 4))));
                a[mi][3] = __float_as_uint(*(const float*)(A + SWZ128((uint32_t)((r + 8 + g) * 128 + (kc + t + 4) * 4))));
            }
#pragma unroll
            for (int j = 0; j < 8; j++) {
                int nr = wx * 64 + j * 8 + g;
                unsigned b0 = __float_as_uint(*(const float*)(Bm + SWZ128((uint32_t)(nr * 128 + (kc + t) * 4))));
                unsigned b1 = __float_as_uint(*(const float*)(Bm + SWZ128((uint32_t)(nr * 128 + (kc + t + 4) * 4))));
                mma8(acc[0][j][0], acc[0][j][1], acc[0][j][2], acc[0][j][3],
                     a[0][0], a[0][1], a[0][2], a[0][3], b0, b1);
                mma8(acc[1][j][0], acc[1][j][1], acc[1][j][2], acc[1][j][3],
                     a[1][0], a[1][1], a[1][2], a[1][3], b0, b1);
            }
        }
        __syncthreads();
        if (kt + 2 < 32) { load_tile(kt + 2, st); CP_COMMIT(); }
    }

    // Epilogue: bias + store
#pragma unroll
    for (int j = 0; j < 8; j++) {
        const int cglob = n0 + wx * 64 + j * 8 + 2 * t;
        const int h = cglob >> 6;
        const int hd = cglob & 63;
        const float b0v = bias[cglob];
        const float b1v = bias[cglob + 1];
#pragma unroll
        for (int mi = 0; mi < 2; mi++) {
#pragma unroll
            for (int half = 0; half < 2; half++) {
                int r = m0 + wy * 32 + mi * 16 + g + half * 8;
                int b = r >> 11;
                int s = r & (SS - 1);
                float v0 = acc[mi][j][half * 2 + 0] + b0v;
                float v1 = acc[mi][j][half * 2 + 1] + b1v;
                if (which == 2) {
                    float* vb2 = dst + ((size_t)(b * HH + h) * HD) * SS;
                    vb2[(size_t)hd * SS + s] = v0;
                    vb2[(size_t)(hd + 1) * SS + s] = v1;
                } else {
                    *(float2*)&dst[((size_t)((b * HH + h) * SS) + s) * HD + hd] =
                        make_float2(v0, v1);
                }
            }
        }
    }
}

// ---------------------------------------------------------------------------
// Flash attention v2: BM=128 q-rows/CTA, BN=64 k-tile, warp owns 16 full rows.
// Softmax entirely in registers (intra-quad shfl), per-warp P staging smem,
// Q persistent in registers, cp.async double-buffered K/V.
// ---------------------------------------------------------------------------
#define ALD 68
#define ATILE (64 * ALD)                    // floats per K or V tile
#define KS_OFF 0                            // 2 stages K
#define VS_OFF (2 * ATILE)                  // 2 stages V
#define PW_OFF (4 * ATILE)                  // 8 warps x 16 x ALD
#define ATTN_SMEM_FLOATS (4 * ATILE + 8 * 16 * ALD)

__global__ __launch_bounds__(256) void attn_kernel(
    const float* __restrict__ qin, float* __restrict__ out) {
    float* smf = (float*)dynsmem;
    const uint32_t sb = smem_u32(dynsmem);

    const int qt = blockIdx.x;
    const int h  = blockIdx.y;
    const int b  = blockIdx.z;
    const int q0 = qt * 128;
    const int klen = g_klen[b];
    const int qlen = g_qlen[b];

    const int tid = threadIdx.x;
    const int lane = tid & 31;
    const int w = tid >> 5;          // warp id = q-row band
    const int g = lane >> 2;
    const int t = lane & 3;

    // Fully padded q-block: residual only.
    if (q0 >= qlen) {
#pragma unroll
        for (int i = 0; i < 8; i++) {
            int id = tid + 256 * i;
            int row = id >> 4;
            int cf = (id & 15) * 4;
            size_t oidx = (size_t)(b * SS + q0 + row) * DD + h * HD + cf;
            *(float4*)&out[oidx] = *(const float4*)&qin[oidx];
        }
        return;
    }

    const float* Qb = g_Q + (size_t)((b * HH + h) * SS) * HD;
    const float* Kb = g_K + (size_t)((b * HH + h) * SS) * HD;
    const float* Vb = g_V + (size_t)((b * HH + h) * HD) * SS;

    // Persistent Q fragments: rows [q0 + w*16, +16), all 64 d.
    const int qr = q0 + w * 16;
    unsigned qf[8][4];
#pragma unroll
    for (int kb = 0; kb < 8; kb++) {
        int kc = kb * 8;
        qf[kb][0] = tf32u(Qb[(size_t)(qr + g) * HD + kc + t]);
        qf[kb][1] = tf32u(Qb[(size_t)(qr + 8 + g) * HD + kc + t]);
        qf[kb][2] = tf32u(Qb[(size_t)(qr + g) * HD + kc + t + 4]);
        qf[kb][3] = tf32u(Qb[(size_t)(qr + 8 + g) * HD + kc + t + 4]);
    }

    float m0r = -INFINITY, m1r = -INFINITY;
    float l0 = 0.0f, l1 = 0.0f;
    float acc[8][4] = {};
    float* Pw = smf + PW_OFF + w * 16 * ALD;

    const int kend = min(klen, q0 + 128);
    const int nt = (kend + 63) >> 6;

    // FULL-tile K/V load: 4 iterations x 256 threads x 16B covers 64x64 floats.
    auto load_kv = [&](int ti, int st) {
        const int k0 = ti * 64;
        const uint32_t kbase = sb + (uint32_t)(KS_OFF + st * ATILE) * 4;
        const uint32_t vbase = sb + (uint32_t)(VS_OFF + st * ATILE) * 4;
#pragma unroll
        for (int i = 0; i < 4; i++) {
            int id = tid + 256 * i;
            int row = id >> 4;          // 0..63
            int cf = (id & 15) * 4;     // 0..60
            cp16(kbase + (uint32_t)(row * ALD + cf) * 4, Kb + (size_t)(k0 + row) * HD + cf);
            cp16(vbase + (uint32_t)(row * ALD + cf) * 4, Vb + (size_t)row * SS + k0 + cf);
        }
    };

    load_kv(0, 0); CP_COMMIT();

    for (int ti = 0; ti < nt; ti++) {
        const int k0 = ti * 64;
        const int st = ti & 1;
        __syncthreads();   // prior reads of the stage being overwritten are done
        if (ti + 1 < nt) { load_kv(ti + 1, (ti + 1) & 1); CP_COMMIT(); CP_WAIT1(); }
        else CP_WAIT0();
        __syncthreads();   // staged K/V visible to all warps

        const float* Ks = smf + KS_OFF + st * ATILE;   // [kpos][d]
        const float* Vt = smf + VS_OFF + st * ATILE;   // [d][kpos]

        // S = Q K^T : warp rows 16 x cols 64
        float s[8][4] = {};
#pragma unroll
        for (int kb = 0; kb < 8; kb++) {
            int kc = kb * 8;
#pragma unroll
            for (int j = 0; j < 4; j++) {
                int nr0 = (2 * j) * 8 + g;
                int nr1 = (2 * j + 1) * 8 + g;
                unsigned b00 = __float_as_uint(Ks[nr0 * ALD + kc + t]);
                unsigned b01 = __float_as_uint(Ks[nr0 * ALD + kc + t + 4]);
                unsigned b10 = __float_as_uint(Ks[nr1 * ALD + kc + t]);
                unsigned b11 = __float_as_uint(Ks[nr1 * ALD + kc + t + 4]);
                mma8(s[2 * j][0], s[2 * j][1], s[2 * j][2], s[2 * j][3],
                     qf[kb][0], qf[kb][1], qf[kb][2], qf[kb][3], b00, b01);
                mma8(s[2 * j + 1][0], s[2 * j + 1][1], s[2 * j + 1][2], s[2 * j + 1][3],
                     qf[kb][0], qf[kb][1], qf[kb][2], qf[kb][3], b10, b11);
            }
        }

        // scale + mask in registers
        const int qq0 = qr + g;
        const int qq1 = qr + 8 + g;
#pragma unroll
        for (int j = 0; j < 8; j++) {
            int c0 = k0 + j * 8 + 2 * t;
            int c1 = c0 + 1;
            s[j][0] = (c0 > qq0 || c0 >= klen) ? -INFINITY : s[j][0] * 0.125f;
            s[j][1] = (c1 > qq0 || c1 >= klen) ? -INFINITY : s[j][1] * 0.125f;
            s[j][2] = (c0 > qq1 || c0 >= klen) ? -INFINITY : s[j][2] * 0.125f;
            s[j][3] = (c1 > qq1 || c1 >= klen) ? -INFINITY : s[j][3] * 0.125f;
        }

        // row max (registers + intra-quad shfl)
        float mt0 = -INFINITY, mt1 = -INFINITY;
#pragma unroll
        for (int j = 0; j < 8; j++) {
            mt0 = fmaxf(mt0, fmaxf(s[j][0], s[j][1]));
            mt1 = fmaxf(mt1, fmaxf(s[j][2], s[j][3]));
        }
        mt0 = fmaxf(mt0, __shfl_xor_sync(0xffffffffu, mt0, 1));
        mt0 = fmaxf(mt0, __shfl_xor_sync(0xffffffffu, mt0, 2));
        mt1 = fmaxf(mt1, __shfl_xor_sync(0xffffffffu, mt1, 1));
        mt1 = fmaxf(mt1, __shfl_xor_sync(0xffffffffu, mt1, 2));

        float mn0 = fmaxf(m0r, mt0);
        float mn1 = fmaxf(m1r, mt1);
        float alpha0, alpha1, sum0 = 0.0f, sum1 = 0.0f;

        if (mn0 == -INFINITY) {
            alpha0 = 1.0f;
#pragma unroll
            for (int j = 0; j < 8; j++) { s[j][0] = 0.0f; s[j][1] = 0.0f; }
        } else {
            alpha0 = (m0r == -INFINITY) ? 0.0f : __expf(m0r - mn0);
#pragma unroll
            for (int j = 0; j < 8; j++) {
                s[j][0] = __expf(s[j][0] - mn0);
                s[j][1] = __expf(s[j][1] - mn0);
                sum0 += s[j][0] + s[j][1];
            }
        }
        if (mn1 == -INFINITY) {
            alpha1 = 1.0f;
#pragma unroll
            for (int j = 0; j < 8; j++) { s[j][2] = 0.0f; s[j][3] = 0.0f; }
        } else {
            alpha1 = (m1r == -INFINITY) ? 0.0f : __expf(m1r - mn1);
#pragma unroll
            for (int j = 0; j < 8; j++) {
                s[j][2] = __expf(s[j][2] - mn1);
                s[j][3] = __expf(s[j][3] - mn1);
                sum1 += s[j][2] + s[j][3];
            }
        }
        sum0 += __shfl_xor_sync(0xffffffffu, sum0, 1);
        sum0 += __shfl_xor_sync(0xffffffffu, sum0, 2);
        sum1 += __shfl_xor_sync(0xffffffffu, sum1, 1);
        sum1 += __shfl_xor_sync(0xffffffffu, sum1, 2);
        l0 = l0 * alpha0 + sum0;  m0r = mn0;
        l1 = l1 * alpha1 + sum1;  m1r = mn1;

        // O *= alpha
#pragma unroll
        for (int j = 0; j < 8; j++) {
            acc[j][0] *= alpha0; acc[j][1] *= alpha0;
            acc[j][2] *= alpha1; acc[j][3] *= alpha1;
        }

        // stage P (tf32-rounded) into per-warp smem, then PV
#pragma unroll
        for (int j = 0; j < 8; j++) {
            int c = j * 8 + 2 * t;
            *(float2*)&Pw[g * ALD + c] = make_float2(tf32f(s[j][0]), tf32f(s[j][1]));
            *(float2*)&Pw[(g + 8) * ALD + c] = make_float2(tf32f(s[j][2]), tf32f(s[j][3]));
        }
        __syncwarp();

#pragma unroll
        for (int kb = 0; kb < 8; kb++) {
            int kc = kb * 8;
            unsigned a0 = __float_as_uint(Pw[g * ALD + kc + t]);
            unsigned a1 = __float_as_uint(Pw[(g + 8) * ALD + kc + t]);
            unsigned a2 = __float_as_uint(Pw[g * ALD + kc + t + 4]);
            unsigned a3 = __float_as_uint(Pw[(g + 8) * ALD + kc + t + 4]);
#pragma unroll
            for (int j = 0; j < 8; j++) {
                int nr = j * 8 + g;   // d index
                unsigned b0 = __float_as_uint(Vt[nr * ALD + kc + t]);
                unsigned b1 = __float_as_uint(Vt[nr * ALD + kc + t + 4]);
                mma8(acc[j][0], acc[j][1], acc[j][2], acc[j][3], a0, a1, a2, a3, b0, b1);
            }
        }
        __syncwarp();   // P smem reads done before next tile's stores
    }

    // Epilogue: normalize, residual, query-padding override.
    float inv0 = (l0 > 0.0f) ? (1.0f / l0) : 0.0f;
    float inv1 = (l1 > 0.0f) ? (1.0f / l1) : 0.0f;
    const int qq0 = qr + g;
    const int qq1 = qr + 8 + g;
#pragma unroll
    for (int j = 0; j < 8; j++) {
        int c = j * 8 + 2 * t;
        {
            size_t oidx = (size_t)(b * SS + qq0) * DD + h * HD + c;
            float2 r2 = *(const float2*)&qin[oidx];
            float2 o = (qq0 >= qlen) ? r2
                     : make_float2(acc[j][0] * inv0 + r2.x, acc[j][1] * inv0 + r2.y);
            *(float2*)&out[oidx] = o;
        }
        {
            size_t oidx = (size_t)(b * SS + qq1) * DD + h * HD + c;
            float2 r2 = *(const float2*)&qin[oidx];
            float2 o = (qq1 >= qlen) ? r2
                     : make_float2(acc[j][2] * inv1 + r2.x, acc[j][3] * inv1 + r2.y);
            *(float2*)&out[oidx] = o;
        }
    }
}

// ---------------------------------------------------------------------------
extern "C" void kernel_launch(void* const* d_in, const int* in_sizes, int n_in,
                              void* d_out, int out_size) {
    const float* q  = (const float*)d_in[0];
    const float* k  = (const float*)d_in[1];
    const float* v  = (const float*)d_in[2];
    const float* Wq = (const float*)d_in[3];
    const float* bq = (const float*)d_in[4];
    const float* Wk = (const float*)d_in[5];
    const float* bk = (const float*)d_in[6];
    const float* Wv = (const float*)d_in[7];
    const float* bv = (const float*)d_in[8];
    const unsigned char* km = (const unsigned char*)d_in[9];
    const unsigned char* qm = (const unsigned char*)d_in[10];
    float* out = (float*)d_out;

    static bool attr_set = false;
    if (!attr_set) {
        cudaFuncSetAttribute(attn_kernel,
                             cudaFuncAttributeMaxDynamicSharedMemorySize,
                             ATTN_SMEM_FLOATS * (int)sizeof(float));
        cudaFuncSetAttribute(proj_kernel,
                             cudaFuncAttributeMaxDynamicSharedMemorySize,
                             PROJ_SMEM);
        attr_set = true;
    }

    dim3 pg(DD / 128, (BB * SS) / 128, 3);
    proj_kernel<<<pg, 256, PROJ_SMEM>>>(q, k, v, Wq, Wk, Wv, bq, bk, bv, km, qm);

    dim3 ag(SS / 128, HH, BB);
    attn_kernel<<<ag, 256, ATTN_SMEM_FLOATS * (int)sizeof(float)>>>(q, out);
}

// round 11
// speedup vs baseline: 1.0063x; 1.0063x over previous
#include <cuda_runtime.h>
#include <math.h>
#include <stdint.h>

#define BB 2
#define SS 2048
#define DD 1024
#define HH 16
#define HD 64

// Single dynamic-smem declaration shared by all kernels.
extern __shared__ char dynsmem[];

// Scratch: projected Q,K in [B,H,S,HD]; V transposed in [B,H,HD,S]
__device__ float g_Q[BB * HH * SS * HD];
__device__ float g_K[BB * HH * SS * HD];
__device__ float g_V[BB * HH * SS * HD];   // [B,H,HD,S] layout!
__device__ int g_klen[BB];
__device__ int g_qlen[BB];

// ---------------------------------------------------------------------------
// helpers
// ---------------------------------------------------------------------------
__device__ __forceinline__ uint32_t smem_u32(const void* p) {
    uint32_t a;
    asm("{ .reg .u64 t; cvta.to.shared.u64 t, %1; cvt.u32.u64 %0, t; }" : "=r"(a) : "l"(p));
    return a;
}
#define SWZ128(x) ((x) ^ (((x) >> 3) & 0x70))

__device__ __forceinline__ void cp16(uint32_t dst, const void* src) {
    asm volatile("cp.async.cg.shared.global [%0], [%1], 16;" :: "r"(dst), "l"(src) : "memory");
}
#define CP_COMMIT() asm volatile("cp.async.commit_group;" ::: "memory")
#define CP_WAIT0() asm volatile("cp.async.wait_group 0;" ::: "memory")
#define CP_WAIT1() asm volatile("cp.async.wait_group 1;" ::: "memory")

__device__ __forceinline__ unsigned tf32u(float x) {
    unsigned u; asm("cvt.rna.tf32.f32 %0, %1;" : "=r"(u) : "f"(x)); return u;
}
__device__ __forceinline__ float tf32f(float x) {
    return __uint_as_float(tf32u(x));
}
__device__ __forceinline__ void mma8(float& c0, float& c1, float& c2, float& c3,
                                     unsigned a0, unsigned a1, unsigned a2, unsigned a3,
                                     unsigned b0, unsigned b1) {
    asm volatile(
        "mma.sync.aligned.m16n8k8.row.col.f32.tf32.tf32.f32 "
        "{%0,%1,%2,%3},{%4,%5,%6,%7},{%8,%9},{%0,%1,%2,%3};"
        : "+f"(c0), "+f"(c1), "+f"(c2), "+f"(c3)
        : "r"(a0), "r"(a1), "r"(a2), "r"(a3), "r"(b0), "r"(b1));
}

// ---------------------------------------------------------------------------
// Projection GEMM, tf32 mma.sync. BM=128, BN=128 (2 heads), BK=32.
// 8 warps in 4(m)x2(n); warp tile 32x64. 2-stage cp.async double buffer.
// CTA (0,0,0) additionally computes the mask lengths (folds len_kernel).
// blockIdx.z selects projection: 0->g_Q, 1->g_K, 2->g_V ([B,H,HD,S]).
// ---------------------------------------------------------------------------
#define PSTAGE 32768         // A 16KB + B 16KB
#define PB_OFF 16384
#define PROJ_SMEM (2 * PSTAGE)

__global__ __launch_bounds__(256, 2) void proj_kernel(
    const float* __restrict__ q, const float* __restrict__ k, const float* __restrict__ v,
    const float* __restrict__ Wq, const float* __restrict__ Wk, const float* __restrict__ Wv,
    const float* __restrict__ bq, const float* __restrict__ bk, const float* __restrict__ bv,
    const unsigned char* __restrict__ km, const unsigned char* __restrict__ qm) {
    char* smem = dynsmem;
    const uint32_t sb = smem_u32(smem);
    const int tid = threadIdx.x;
    const int lane = tid & 31;
    const int wid = tid >> 5;
    const int g = lane >> 2;
    const int t = lane & 3;
    const int wy = wid & 3;    // m band (32 rows)
    const int wx = wid >> 2;   // n half (64 cols)

    // --- fold mask-length computation into one CTA (hidden in the wave) ---
    __shared__ int cnt[4];     // klen[0], klen[1], qlen[0], qlen[1]
    if (blockIdx.x == 0 && blockIdx.y == 0 && blockIdx.z == 0) {
        if (tid < 4) cnt[tid] = 0;
        __syncthreads();
        int wk = (km[1] | km[2] | km[3]) ? 1 : 4;
        int wq = (qm[1] | qm[2] | qm[3]) ? 1 : 4;
#pragma unroll
        for (int b = 0; b < BB; b++) {
            int ck = 0, cq = 0;
            for (int i = tid; i < SS * wk; i += 256) ck += (km[(size_t)b * SS * wk + i] != 0);
            for (int i = tid; i < SS * wq; i += 256) cq += (qm[(size_t)b * SS * wq + i] != 0);
#pragma unroll
            for (int o = 16; o > 0; o >>= 1) {
                ck += __shfl_down_sync(0xffffffffu, ck, o);
                cq += __shfl_down_sync(0xffffffffu, cq, o);
            }
            if (lane == 0) { atomicAdd(&cnt[b], ck); atomicAdd(&cnt[2 + b], cq); }
        }
        __syncthreads();
        if (tid < 2) { g_klen[tid] = cnt[tid]; g_qlen[tid] = cnt[2 + tid]; }
    }

    const int which = blockIdx.z;
    const float* X = (which == 0) ? q : (which == 1) ? k : v;
    const float* W = (which == 0) ? Wq : (which == 1) ? Wk : Wv;
    const float* bias = (which == 0) ? bq : (which == 1) ? bk : bv;
    float* dst = (which == 0) ? g_Q : (which == 1) ? g_K : g_V;

    const int n0 = blockIdx.x * 128;
    const int m0 = blockIdx.y * 128;

    const int r0 = tid >> 3;         // 0..31, +32 per i
    const int cb = (tid & 7) * 16;   // byte col of 16B chunk in 128B row

    float acc[2][8][4] = {};

    auto load_tile = [&](int kt, int stage) {
        const int kf = kt * 32 + (cb >> 2);
        const uint32_t abase = sb + stage * PSTAGE;
#pragma unroll
        for (int i = 0; i < 4; i++) {
            int r = r0 + 32 * i;
            uint32_t sw = SWZ128((uint32_t)(r * 128 + cb));
            cp16(abase + sw, X + (size_t)(m0 + r) * DD + kf);
            cp16(abase + PB_OFF + sw, W + (size_t)(n0 + r) * DD + kf);
        }
    };

    load_tile(0, 0); CP_COMMIT();
    load_tile(1, 1); CP_COMMIT();

    for (int kt = 0; kt < 32; kt++) {
        const int st = kt & 1;
        if (kt < 30) CP_WAIT1(); else CP_WAIT0();
        __syncthreads();

        const char* A = smem + st * PSTAGE;
        const char* Bm = A + PB_OFF;
#pragma unroll
        for (int ks = 0; ks < 4; ks++) {
            const int kc = ks * 8;
            unsigned a[2][4];
#pragma unroll
            for (int mi = 0; mi < 2; mi++) {
                int r = wy * 32 + mi * 16;
                a[mi][0] = __float_as_uint(*(const float*)(A + SWZ128((uint32_t)((r + g) * 128 + (kc + t) * 4))));
                a[mi][1] = __float_as_uint(*(const float*)(A + SWZ128((uint32_t)((r + 8 + g) * 128 + (kc + t) * 4))));
                a[mi][2] = __float_as_uint(*(const float*)(A + SWZ128((uint32_t)((r + g) * 128 + (kc + t + 4) * 4))));
                a[mi][3] = __float_as_uint(*(const float*)(A + SWZ128((uint32_t)((r + 8 + g) * 128 + (kc + t + 4) * 4))));
            }
#pragma unroll
            for (int j = 0; j < 8; j++) {
                int nr = wx * 64 + j * 8 + g;
                unsigned b0 = __float_as_uint(*(const float*)(Bm + SWZ128((uint32_t)(nr * 128 + (kc + t) * 4))));
                unsigned b1 = __float_as_uint(*(const float*)(Bm + SWZ128((uint32_t)(nr * 128 + (kc + t + 4) * 4))));
                mma8(acc[0][j][0], acc[0][j][1], acc[0][j][2], acc[0][j][3],
                     a[0][0], a[0][1], a[0][2], a[0][3], b0, b1);
                mma8(acc[1][j][0], acc[1][j][1], acc[1][j][2], acc[1][j][3],
                     a[1][0], a[1][1], a[1][2], a[1][3], b0, b1);
            }
        }
        __syncthreads();
        if (kt + 2 < 32) { load_tile(kt + 2, st); CP_COMMIT(); }
    }

    // Epilogue: bias + store
#pragma unroll
    for (int j = 0; j < 8; j++) {
        const int cglob = n0 + wx * 64 + j * 8 + 2 * t;
        const int h = cglob >> 6;
        const int hd = cglob & 63;
        const float b0v = bias[cglob];
        const float b1v = bias[cglob + 1];
#pragma unroll
        for (int mi = 0; mi < 2; mi++) {
#pragma unroll
            for (int half = 0; half < 2; half++) {
                int r = m0 + wy * 32 + mi * 16 + g + half * 8;
                int b = r >> 11;
                int s = r & (SS - 1);
                float v0 = acc[mi][j][half * 2 + 0] + b0v;
                float v1 = acc[mi][j][half * 2 + 1] + b1v;
                if (which == 2) {
                    float* vb2 = dst + ((size_t)(b * HH + h) * HD) * SS;
                    vb2[(size_t)hd * SS + s] = v0;
                    vb2[(size_t)(hd + 1) * SS + s] = v1;
                } else {
                    *(float2*)&dst[((size_t)((b * HH + h) * SS) + s) * HD + hd] =
                        make_float2(v0, v1);
                }
            }
        }
    }
}

// ---------------------------------------------------------------------------
// Flash attention v3: BM=128, BN=64, warp owns 16 full rows.
// Q in smem (loaded once, tf32); register softmax; P->A-fragment via
// intra-quad shuffles (no P smem); cp.async double-buffered K/V.
// Smem = Q 34.8K + K 2x17.4K + V 2x17.4K = 104.4KB -> 2 CTAs/SM.
// ---------------------------------------------------------------------------
#define ALD 68
#define ATILE (64 * ALD)
#define QS_OFF 0                         // 128 x ALD
#define KS_OFF (128 * ALD)               // 2 stages
#define VS_OFF (KS_OFF + 2 * ATILE)      // 2 stages
#define ATTN_SMEM_FLOATS (128 * ALD + 4 * ATILE)

__global__ __launch_bounds__(256, 2) void attn_kernel(
    const float* __restrict__ qin, float* __restrict__ out) {
    float* smf = (float*)dynsmem;
    const uint32_t sb = smem_u32(dynsmem);

    const int qt = blockIdx.x;
    const int h  = blockIdx.y;
    const int b  = blockIdx.z;
    const int q0 = qt * 128;
    const int klen = g_klen[b];
    const int qlen = g_qlen[b];

    const int tid = threadIdx.x;
    const int lane = tid & 31;
    const int w = tid >> 5;          // warp id = q-row band
    const int g = lane >> 2;
    const int t = lane & 3;

    // Fully padded q-block: residual only.
    if (q0 >= qlen) {
#pragma unroll
        for (int i = 0; i < 8; i++) {
            int id = tid + 256 * i;
            int row = id >> 4;
            int cf = (id & 15) * 4;
            size_t oidx = (size_t)(b * SS + q0 + row) * DD + h * HD + cf;
            *(float4*)&out[oidx] = *(const float4*)&qin[oidx];
        }
        return;
    }

    const float* Qb = g_Q + (size_t)((b * HH + h) * SS) * HD;
    const float* Kb = g_K + (size_t)((b * HH + h) * SS) * HD;
    const float* Vb = g_V + (size_t)((b * HH + h) * HD) * SS;

    const int kend = min(klen, q0 + 128);
    const int nt = (kend + 63) >> 6;

    // FULL-tile K/V load: 4 iters x 256 threads x 16B = 64x64 floats each.
    auto load_kv = [&](int ti, int st) {
        const int k0 = ti * 64;
        const uint32_t kbase = sb + (uint32_t)(KS_OFF + st * ATILE) * 4;
        const uint32_t vbase = sb + (uint32_t)(VS_OFF + st * ATILE) * 4;
#pragma unroll
        for (int i = 0; i < 4; i++) {
            int id = tid + 256 * i;
            int row = id >> 4;          // 0..63
            int cf = (id & 15) * 4;     // 0..60
            cp16(kbase + (uint32_t)(row * ALD + cf) * 4, Kb + (size_t)(k0 + row) * HD + cf);
            cp16(vbase + (uint32_t)(row * ALD + cf) * 4, Vb + (size_t)row * SS + k0 + cf);
        }
    };

    load_kv(0, 0); CP_COMMIT();

    // Q tile -> smem once (tf32-rounded).
#pragma unroll
    for (int i = 0; i < 8; i++) {
        int id = tid + 256 * i;
        int row = id >> 4;              // 0..127
        int cf = (id & 15) * 4;
        float4 a = *(const float4*)&Qb[(size_t)(q0 + row) * HD + cf];
        float* qs = smf + QS_OFF + row * ALD + cf;
        qs[0] = tf32f(a.x); qs[1] = tf32f(a.y); qs[2] = tf32f(a.z); qs[3] = tf32f(a.w);
    }

    const int qr = q0 + w * 16;
    const float* Qw = smf + QS_OFF + (w * 16) * ALD;   // warp's 16 rows

    float m0r = -INFINITY, m1r = -INFINITY;
    float l0 = 0.0f, l1 = 0.0f;
    float acc[8][4] = {};

    for (int ti = 0; ti < nt; ti++) {
        const int k0 = ti * 64;
        const int st = ti & 1;
        __syncthreads();   // prior reads of overwritten stage done; Q visible on ti=0
        if (ti + 1 < nt) { load_kv(ti + 1, (ti + 1) & 1); CP_COMMIT(); CP_WAIT1(); }
        else CP_WAIT0();
        __syncthreads();   // staged K/V visible to all warps

        const float* Ks = smf + KS_OFF + st * ATILE;   // [kpos][d]
        const float* Vt = smf + VS_OFF + st * ATILE;   // [d][kpos]

        // S = Q K^T : warp rows 16 x cols 64 (Q fragments from smem)
        float s[8][4] = {};
#pragma unroll
        for (int kb = 0; kb < 8; kb++) {
            int kc = kb * 8;
            unsigned a0 = __float_as_uint(Qw[g * ALD + kc + t]);
            unsigned a1 = __float_as_uint(Qw[(g + 8) * ALD + kc + t]);
            unsigned a2 = __float_as_uint(Qw[g * ALD + kc + t + 4]);
            unsigned a3 = __float_as_uint(Qw[(g + 8) * ALD + kc + t + 4]);
#pragma unroll
            for (int j = 0; j < 4; j++) {
                int nr0 = (2 * j) * 8 + g;
                int nr1 = (2 * j + 1) * 8 + g;
                unsigned b00 = __float_as_uint(Ks[nr0 * ALD + kc + t]);
                unsigned b01 = __float_as_uint(Ks[nr0 * ALD + kc + t + 4]);
                unsigned b10 = __float_as_uint(Ks[nr1 * ALD + kc + t]);
                unsigned b11 = __float_as_uint(Ks[nr1 * ALD + kc + t + 4]);
                mma8(s[2 * j][0], s[2 * j][1], s[2 * j][2], s[2 * j][3],
                     a0, a1, a2, a3, b00, b01);
                mma8(s[2 * j + 1][0], s[2 * j + 1][1], s[2 * j + 1][2], s[2 * j + 1][3],
                     a0, a1, a2, a3, b10, b11);
            }
        }

        // scale + mask in registers
        const int qq0 = qr + g;
        const int qq1 = qr + 8 + g;
#pragma unroll
        for (int j = 0; j < 8; j++) {
            int c0 = k0 + j * 8 + 2 * t;
            int c1 = c0 + 1;
            s[j][0] = (c0 > qq0 || c0 >= klen) ? -INFINITY : s[j][0] * 0.125f;
            s[j][1] = (c1 > qq0 || c1 >= klen) ? -INFINITY : s[j][1] * 0.125f;
            s[j][2] = (c0 > qq1 || c0 >= klen) ? -INFINITY : s[j][2] * 0.125f;
            s[j][3] = (c1 > qq1 || c1 >= klen) ? -INFINITY : s[j][3] * 0.125f;
        }

        // row max (registers + intra-quad shfl)
        float mt0 = -INFINITY, mt1 = -INFINITY;
#pragma unroll
        for (int j = 0; j < 8; j++) {
            mt0 = fmaxf(mt0, fmaxf(s[j][0], s[j][1]));
            mt1 = fmaxf(mt1, fmaxf(s[j][2], s[j][3]));
        }
        mt0 = fmaxf(mt0, __shfl_xor_sync(0xffffffffu, mt0, 1));
        mt0 = fmaxf(mt0, __shfl_xor_sync(0xffffffffu, mt0, 2));
        mt1 = fmaxf(mt1, __shfl_xor_sync(0xffffffffu, mt1, 1));
        mt1 = fmaxf(mt1, __shfl_xor_sync(0xffffffffu, mt1, 2));

        float mn0 = fmaxf(m0r, mt0);
        float mn1 = fmaxf(m1r, mt1);
        float alpha0, alpha1, sum0 = 0.0f, sum1 = 0.0f;

        if (mn0 == -INFINITY) {
            alpha0 = 1.0f;
#pragma unroll
            for (int j = 0; j < 8; j++) { s[j][0] = 0.0f; s[j][1] = 0.0f; }
        } else {
            alpha0 = (m0r == -INFINITY) ? 0.0f : __expf(m0r - mn0);
#pragma unroll
            for (int j = 0; j < 8; j++) {
                s[j][0] = __expf(s[j][0] - mn0);
                s[j][1] = __expf(s[j][1] - mn0);
                sum0 += s[j][0] + s[j][1];
            }
        }
        if (mn1 == -INFINITY) {
            alpha1 = 1.0f;
#pragma unroll
            for (int j = 0; j < 8; j++) { s[j][2] = 0.0f; s[j][3] = 0.0f; }
        } else {
            alpha1 = (m1r == -INFINITY) ? 0.0f : __expf(m1r - mn1);
#pragma unroll
            for (int j = 0; j < 8; j++) {
                s[j][2] = __expf(s[j][2] - mn1);
                s[j][3] = __expf(s[j][3] - mn1);
                sum1 += s[j][2] + s[j][3];
            }
        }
        sum0 += __shfl_xor_sync(0xffffffffu, sum0, 1);
        sum0 += __shfl_xor_sync(0xffffffffu, sum0, 2);
        sum1 += __shfl_xor_sync(0xffffffffu, sum1, 1);
        sum1 += __shfl_xor_sync(0xffffffffu, sum1, 2);
        l0 = l0 * alpha0 + sum0;  m0r = mn0;
        l1 = l1 * alpha1 + sum1;  m1r = mn1;

        // O *= alpha; round P to tf32 (rna) in place
#pragma unroll
        for (int j = 0; j < 8; j++) {
            acc[j][0] *= alpha0; acc[j][1] *= alpha0;
            acc[j][2] *= alpha1; acc[j][3] *= alpha1;
            s[j][0] = tf32f(s[j][0]); s[j][1] = tf32f(s[j][1]);
            s[j][2] = tf32f(s[j][2]); s[j][3] = tf32f(s[j][3]);
        }

        // PV: A-fragment built by intra-quad shuffles from s (C-layout).
        // P[row r][col kb*8+c] lives in lane (r%8)*4 + (c>>1), reg s[kb][(c&1) + 2*(r>=8)].
        const int srcA = (lane & ~3) | (t >> 1);
        const int srcB = srcA + 2;
        const bool odd = (t & 1);
#pragma unroll
        for (int kb = 0; kb < 8; kb++) {
            float vA0 = __shfl_sync(0xffffffffu, s[kb][0], srcA);
            float vA1 = __shfl_sync(0xffffffffu, s[kb][1], srcA);
            float vA2 = __shfl_sync(0xffffffffu, s[kb][2], srcA);
            float vA3 = __shfl_sync(0xffffffffu, s[kb][3], srcA);
            float vB0 = __shfl_sync(0xffffffffu, s[kb][0], srcB);
            float vB1 = __shfl_sync(0xffffffffu, s[kb][1], srcB);
            float vB2 = __shfl_sync(0xffffffffu, s[kb][2], srcB);
            float vB3 = __shfl_sync(0xffffffffu, s[kb][3], srcB);
            unsigned a0 = __float_as_uint(odd ? vA1 : vA0);
            unsigned a1 = __float_as_uint(odd ? vA3 : vA2);
            unsigned a2 = __float_as_uint(odd ? vB1 : vB0);
            unsigned a3 = __float_as_uint(odd ? vB3 : vB2);
            int kc = kb * 8;
#pragma unroll
            for (int j = 0; j < 8; j++) {
                int nr = j * 8 + g;   // d index
                unsigned b0 = __float_as_uint(Vt[nr * ALD + kc + t]);
                unsigned b1 = __float_as_uint(Vt[nr * ALD + kc + t + 4]);
                mma8(acc[j][0], acc[j][1], acc[j][2], acc[j][3], a0, a1, a2, a3, b0, b1);
            }
        }
    }

    // Epilogue: normalize, residual, query-padding override.
    float inv0 = (l0 > 0.0f) ? (1.0f / l0) : 0.0f;
    float inv1 = (l1 > 0.0f) ? (1.0f / l1) : 0.0f;
    const int qq0 = qr + g;
    const int qq1 = qr + 8 + g;
#pragma unroll
    for (int j = 0; j < 8; j++) {
        int c = j * 8 + 2 * t;
        {
            size_t oidx = (size_t)(b * SS + qq0) * DD + h * HD + c;
            float2 r2 = *(const float2*)&qin[oidx];
            float2 o = (qq0 >= qlen) ? r2
                     : make_float2(acc[j][0] * inv0 + r2.x, acc[j][1] * inv0 + r2.y);
            *(float2*)&out[oidx] = o;
        }
        {
            size_t oidx = (size_t)(b * SS + qq1) * DD + h * HD + c;
            float2 r2 = *(const float2*)&qin[oidx];
            float2 o = (qq1 >= qlen) ? r2
                     : make_float2(acc[j][2] * inv1 + r2.x, acc[j][3] * inv1 + r2.y);
            *(float2*)&out[oidx] = o;
        }
    }
}

// ---------------------------------------------------------------------------
extern "C" void kernel_launch(void* const* d_in, const int* in_sizes, int n_in,
                              void* d_out, int out_size) {
    const float* q  = (const float*)d_in[0];
    const float* k  = (const float*)d_in[1];
    const float* v  = (const float*)d_in[2];
    const float* Wq = (const float*)d_in[3];
    const float* bq = (const float*)d_in[4];
    const float* Wk = (const float*)d_in[5];
    const float* bk = (const float*)d_in[6];
    const float* Wv = (const float*)d_in[7];
    const float* bv = (const float*)d_in[8];
    const unsigned char* km = (const unsigned char*)d_in[9];
    const unsigned char* qm = (const unsigned char*)d_in[10];
    float* out = (float*)d_out;

    static bool attr_set = false;
    if (!attr_set) {
        cudaFuncSetAttribute(attn_kernel,
                             cudaFuncAttributeMaxDynamicSharedMemorySize,
                             ATTN_SMEM_FLOATS * (int)sizeof(float));
        cudaFuncSetAttribute(proj_kernel,
                             cudaFuncAttributeMaxDynamicSharedMemorySize,
                             PROJ_SMEM);
        attr_set = true;
    }

    dim3 pg(DD / 128, (BB * SS) / 128, 3);
    proj_kernel<<<pg, 256, PROJ_SMEM>>>(q, k, v, Wq, Wk, Wv, bq, bk, bv, km, qm);

    dim3 ag(SS / 128, HH, BB);
    attn_kernel<<<ag, 256, ATTN_SMEM_FLOATS * (int)sizeof(float)>>>(q, out);
}

// round 12
// speedup vs baseline: 1.1163x; 1.1093x over previous
#include <cuda_runtime.h>
#include <math.h>
#include <stdint.h>

#define BB 2
#define SS 2048
#define DD 1024
#define HH 16
#define HD 64

// Single dynamic-smem declaration shared by all kernels.
extern __shared__ char dynsmem[];

// Scratch: projected Q,K in [B,H,S,HD]; V transposed in [B,H,HD,S]
__device__ float g_Q[BB * HH * SS * HD];
__device__ float g_K[BB * HH * SS * HD];
__device__ float g_V[BB * HH * SS * HD];   // [B,H,HD,S] layout!
__device__ int g_klen[BB];
__device__ int g_qlen[BB];

// ---------------------------------------------------------------------------
// helpers
// ---------------------------------------------------------------------------
__device__ __forceinline__ uint32_t smem_u32(const void* p) {
    uint32_t a;
    asm("{ .reg .u64 t; cvta.to.shared.u64 t, %1; cvt.u32.u64 %0, t; }" : "=r"(a) : "l"(p));
    return a;
}
#define SWZ128(x) ((x) ^ (((x) >> 3) & 0x70))

__device__ __forceinline__ void cp16(uint32_t dst, const void* src) {
    asm volatile("cp.async.cg.shared.global [%0], [%1], 16;" :: "r"(dst), "l"(src) : "memory");
}
#define CP_COMMIT() asm volatile("cp.async.commit_group;" ::: "memory")
#define CP_WAIT0() asm volatile("cp.async.wait_group 0;" ::: "memory")
#define CP_WAIT1() asm volatile("cp.async.wait_group 1;" ::: "memory")

__device__ __forceinline__ unsigned tf32u(float x) {
    unsigned u; asm("cvt.rna.tf32.f32 %0, %1;" : "=r"(u) : "f"(x)); return u;
}
__device__ __forceinline__ float tf32f(float x) {
    return __uint_as_float(tf32u(x));
}
__device__ __forceinline__ void mma8(float& c0, float& c1, float& c2, float& c3,
                                     unsigned a0, unsigned a1, unsigned a2, unsigned a3,
                                     unsigned b0, unsigned b1) {
    asm volatile(
        "mma.sync.aligned.m16n8k8.row.col.f32.tf32.tf32.f32 "
        "{%0,%1,%2,%3},{%4,%5,%6,%7},{%8,%9},{%0,%1,%2,%3};"
        : "+f"(c0), "+f"(c1), "+f"(c2), "+f"(c3)
        : "r"(a0), "r"(a1), "r"(a2), "r"(a3), "r"(b0), "r"(b1));
}
// ldmatrix x4: one instruction loads 4 fragments (4 scalar-LDS each -> 1 LDSM).
__device__ __forceinline__ void ldsm4(unsigned& r0, unsigned& r1, unsigned& r2, unsigned& r3,
                                      uint32_t addr) {
    asm volatile("ldmatrix.sync.aligned.m8n8.x4.shared.b16 {%0,%1,%2,%3}, [%4];"
                 : "=r"(r0), "=r"(r1), "=r"(r2), "=r"(r3) : "r"(addr));
}

// ---------------------------------------------------------------------------
// Projection GEMM, tf32 mma.sync + ldmatrix. BM=128, BN=128, BK=32.
// 8 warps in 4(m)x2(n); warp tile 32x64. 2-stage cp.async double buffer.
// CTA (0,0,0) additionally computes the mask lengths (folds len_kernel).
// blockIdx.z selects projection: 0->g_Q, 1->g_K, 2->g_V ([B,H,HD,S]).
// ---------------------------------------------------------------------------
#define PSTAGE 32768         // A 16KB + B 16KB
#define PB_OFF 16384
#define PROJ_SMEM (2 * PSTAGE)

__global__ __launch_bounds__(256, 2) void proj_kernel(
    const float* __restrict__ q, const float* __restrict__ k, const float* __restrict__ v,
    const float* __restrict__ Wq, const float* __restrict__ Wk, const float* __restrict__ Wv,
    const float* __restrict__ bq, const float* __restrict__ bk, const float* __restrict__ bv,
    const unsigned char* __restrict__ km, const unsigned char* __restrict__ qm) {
    char* smem = dynsmem;
    const uint32_t sb = smem_u32(smem);
    const int tid = threadIdx.x;
    const int lane = tid & 31;
    const int wid = tid >> 5;
    const int g = lane >> 2;
    const int t = lane & 3;
    const int wy = wid & 3;    // m band (32 rows)
    const int wx = wid >> 2;   // n half (64 cols)

    // --- fold mask-length computation into one CTA (hidden in the wave) ---
    __shared__ int cnt[4];     // klen[0], klen[1], qlen[0], qlen[1]
    if (blockIdx.x == 0 && blockIdx.y == 0 && blockIdx.z == 0) {
        if (tid < 4) cnt[tid] = 0;
        __syncthreads();
        int wk = (km[1] | km[2] | km[3]) ? 1 : 4;
        int wq = (qm[1] | qm[2] | qm[3]) ? 1 : 4;
#pragma unroll
        for (int b = 0; b < BB; b++) {
            int ck = 0, cq = 0;
            for (int i = tid; i < SS * wk; i += 256) ck += (km[(size_t)b * SS * wk + i] != 0);
            for (int i = tid; i < SS * wq; i += 256) cq += (qm[(size_t)b * SS * wq + i] != 0);
#pragma unroll
            for (int o = 16; o > 0; o >>= 1) {
                ck += __shfl_down_sync(0xffffffffu, ck, o);
                cq += __shfl_down_sync(0xffffffffu, cq, o);
            }
            if (lane == 0) { atomicAdd(&cnt[b], ck); atomicAdd(&cnt[2 + b], cq); }
        }
        __syncthreads();
        if (tid < 2) { g_klen[tid] = cnt[tid]; g_qlen[tid] = cnt[2 + tid]; }
    }

    const int which = blockIdx.z;
    const float* X = (which == 0) ? q : (which == 1) ? k : v;
    const float* W = (which == 0) ? Wq : (which == 1) ? Wk : Wv;
    const float* bias = (which == 0) ? bq : (which == 1) ? bk : bv;
    float* dst = (which == 0) ? g_Q : (which == 1) ? g_K : g_V;

    const int n0 = blockIdx.x * 128;
    const int m0 = blockIdx.y * 128;

    const int r0 = tid >> 3;         // 0..31, +32 per i
    const int cb = (tid & 7) * 16;   // byte col of 16B chunk in 128B row

    // ldmatrix lane roles
    const int row_sel = lane & 7;
    const int tl = lane >> 3;        // tile index 0..3
    // A tiles: row += (tl&1)*8, col += (tl>>1)*4 floats
    const uint32_t rowA0 = (uint32_t)((wy * 32 + (tl & 1) * 8 + row_sel) * 128);
    // B tiles: row += (tl>>1)*8 (+pair*16), col += (tl&1)*4 floats
    const uint32_t rowB0 = (uint32_t)((wx * 64 + (tl >> 1) * 8 + row_sel) * 128);

    float acc[2][8][4] = {};

    auto load_tile = [&](int kt, int stage) {
        const int kf = kt * 32 + (cb >> 2);
        const uint32_t abase = sb + stage * PSTAGE;
#pragma unroll
        for (int i = 0; i < 4; i++) {
            int r = r0 + 32 * i;
            uint32_t sw = SWZ128((uint32_t)(r * 128 + cb));
            cp16(abase + sw, X + (size_t)(m0 + r) * DD + kf);
            cp16(abase + PB_OFF + sw, W + (size_t)(n0 + r) * DD + kf);
        }
    };

    load_tile(0, 0); CP_COMMIT();
    load_tile(1, 1); CP_COMMIT();

    for (int kt = 0; kt < 32; kt++) {
        const int st = kt & 1;
        if (kt < 30) CP_WAIT1(); else CP_WAIT0();
        __syncthreads();

        const uint32_t au = sb + st * PSTAGE;
        const uint32_t bu = au + PB_OFF;
#pragma unroll
        for (int ks = 0; ks < 4; ks++) {
            const int kc = ks * 8;
            const uint32_t colA = (uint32_t)((kc + (tl >> 1) * 4) * 4);
            const uint32_t colB = (uint32_t)((kc + (tl & 1) * 4) * 4);
            unsigned a[2][4];
            ldsm4(a[0][0], a[0][1], a[0][2], a[0][3], au + SWZ128(rowA0 + colA));
            ldsm4(a[1][0], a[1][1], a[1][2], a[1][3], au + SWZ128(rowA0 + 16 * 128 + colA));
#pragma unroll
            for (int p = 0; p < 4; p++) {
                unsigned b0, b1, b2, b3;   // b0/b1: j=2p, b2/b3: j=2p+1
                ldsm4(b0, b1, b2, b3, bu + SWZ128(rowB0 + (uint32_t)(p * 16 * 128) + colB));
                const int j0 = 2 * p, j1 = 2 * p + 1;
                mma8(acc[0][j0][0], acc[0][j0][1], acc[0][j0][2], acc[0][j0][3],
                     a[0][0], a[0][1], a[0][2], a[0][3], b0, b1);
                mma8(acc[1][j0][0], acc[1][j0][1], acc[1][j0][2], acc[1][j0][3],
                     a[1][0], a[1][1], a[1][2], a[1][3], b0, b1);
                mma8(acc[0][j1][0], acc[0][j1][1], acc[0][j1][2], acc[0][j1][3],
                     a[0][0], a[0][1], a[0][2], a[0][3], b2, b3);
                mma8(acc[1][j1][0], acc[1][j1][1], acc[1][j1][2], acc[1][j1][3],
                     a[1][0], a[1][1], a[1][2], a[1][3], b2, b3);
            }
        }
        __syncthreads();
        if (kt + 2 < 32) { load_tile(kt + 2, st); CP_COMMIT(); }
    }

    // Epilogue: bias + store
#pragma unroll
    for (int j = 0; j < 8; j++) {
        const int cglob = n0 + wx * 64 + j * 8 + 2 * t;
        const int h = cglob >> 6;
        const int hd = cglob & 63;
        const float b0v = bias[cglob];
        const float b1v = bias[cglob + 1];
#pragma unroll
        for (int mi = 0; mi < 2; mi++) {
#pragma unroll
            for (int half = 0; half < 2; half++) {
                int r = m0 + wy * 32 + mi * 16 + g + half * 8;
                int b = r >> 11;
                int s = r & (SS - 1);
                float v0 = acc[mi][j][half * 2 + 0] + b0v;
                float v1 = acc[mi][j][half * 2 + 1] + b1v;
                if (which == 2) {
                    float* vb2 = dst + ((size_t)(b * HH + h) * HD) * SS;
                    vb2[(size_t)hd * SS + s] = v0;
                    vb2[(size_t)(hd + 1) * SS + s] = v1;
                } else {
                    *(float2*)&dst[((size_t)((b * HH + h) * SS) + s) * HD + hd] =
                        make_float2(v0, v1);
                }
            }
        }
    }
}

// ---------------------------------------------------------------------------
// Flash attention v4: BM=128, BN=64, warp owns 16 full rows.
// Q in smem; register softmax; P->A via intra-quad shuffles; ldmatrix for
// Q/K/V fragments; cp.async double-buffered K/V. 2 CTAs/SM.
// ---------------------------------------------------------------------------
#define ALD 68
#define ATILE (64 * ALD)
#define QS_OFF 0                         // 128 x ALD
#define KS_OFF (128 * ALD)               // 2 stages
#define VS_OFF (KS_OFF + 2 * ATILE)      // 2 stages
#define ATTN_SMEM_FLOATS (128 * ALD + 4 * ATILE)

__global__ __launch_bounds__(256, 2) void attn_kernel(
    const float* __restrict__ qin, float* __restrict__ out) {
    float* smf = (float*)dynsmem;
    const uint32_t sb = smem_u32(dynsmem);

    const int qt = blockIdx.x;
    const int h  = blockIdx.y;
    const int b  = blockIdx.z;
    const int q0 = qt * 128;
    const int klen = g_klen[b];
    const int qlen = g_qlen[b];

    const int tid = threadIdx.x;
    const int lane = tid & 31;
    const int w = tid >> 5;          // warp id = q-row band
    const int g = lane >> 2;
    const int t = lane & 3;

    // Fully padded q-block: residual only.
    if (q0 >= qlen) {
#pragma unroll
        for (int i = 0; i < 8; i++) {
            int id = tid + 256 * i;
            int row = id >> 4;
            int cf = (id & 15) * 4;
            size_t oidx = (size_t)(b * SS + q0 + row) * DD + h * HD + cf;
            *(float4*)&out[oidx] = *(const float4*)&qin[oidx];
        }
        return;
    }

    const float* Qb = g_Q + (size_t)((b * HH + h) * SS) * HD;
    const float* Kb = g_K + (size_t)((b * HH + h) * SS) * HD;
    const float* Vb = g_V + (size_t)((b * HH + h) * HD) * SS;

    const int kend = min(klen, q0 + 128);
    const int nt = (kend + 63) >> 6;

    // FULL-tile K/V load: 4 iters x 256 threads x 16B = 64x64 floats each.
    auto load_kv = [&](int ti, int st) {
        const int k0 = ti * 64;
        const uint32_t kbase = sb + (uint32_t)(KS_OFF + st * ATILE) * 4;
        const uint32_t vbase = sb + (uint32_t)(VS_OFF + st * ATILE) * 4;
#pragma unroll
        for (int i = 0; i < 4; i++) {
            int id = tid + 256 * i;
            int row = id >> 4;          // 0..63
            int cf = (id & 15) * 4;     // 0..60
            cp16(kbase + (uint32_t)(row * ALD + cf) * 4, Kb + (size_t)(k0 + row) * HD + cf);
            cp16(vbase + (uint32_t)(row * ALD + cf) * 4, Vb + (size_t)row * SS + k0 + cf);
        }
    };

    load_kv(0, 0); CP_COMMIT();

    // Q tile -> smem once (tf32-rounded).
#pragma unroll
    for (int i = 0; i < 8; i++) {
        int id = tid + 256 * i;
        int row = id >> 4;              // 0..127
        int cf = (id & 15) * 4;
        float4 a = *(const float4*)&Qb[(size_t)(q0 + row) * HD + cf];
        float* qs = smf + QS_OFF + row * ALD + cf;
        qs[0] = tf32f(a.x); qs[1] = tf32f(a.y); qs[2] = tf32f(a.z); qs[3] = tf32f(a.w);
    }

    const int qr = q0 + w * 16;

    // ldmatrix lane roles
    const int row_sel = lane & 7;
    const int tl = lane >> 3;
    // A (Q): row = w*16 + (tl&1)*8 + row_sel; col floats = (tl>>1)*4 (+kc)
    const uint32_t qa_base = sb + 4u * (uint32_t)(QS_OFF +
                             (w * 16 + (tl & 1) * 8 + row_sel) * ALD + (tl >> 1) * 4);
    // B (K/V): row = (tl>>1)*8 + row_sel (+pair*16); col floats = (tl&1)*4 (+kc)
    const uint32_t bfrag_off = 4u * (uint32_t)(((tl >> 1) * 8 + row_sel) * ALD + (tl & 1) * 4);
    const uint32_t PSTRIDE = 4u * 16u * ALD;   // bytes per j-pair (16 rows)

    float m0r = -INFINITY, m1r = -INFINITY;
    float l0 = 0.0f, l1 = 0.0f;
    float acc[8][4] = {};

    for (int ti = 0; ti < nt; ti++) {
        const int k0 = ti * 64;
        const int st = ti & 1;
        __syncthreads();   // prior reads of overwritten stage done; Q visible on ti=0
        if (ti + 1 < nt) { load_kv(ti + 1, (ti + 1) & 1); CP_COMMIT(); CP_WAIT1(); }
        else CP_WAIT0();
        __syncthreads();   // staged K/V visible to all warps

        const uint32_t ks_u = sb + 4u * (uint32_t)(KS_OFF + st * ATILE);
        const uint32_t vt_u = sb + 4u * (uint32_t)(VS_OFF + st * ATILE);

        // S = Q K^T : warp rows 16 x cols 64
        float s[8][4] = {};
#pragma unroll
        for (int kb = 0; kb < 8; kb++) {
            const uint32_t kcb = (uint32_t)(kb * 32);   // kc*4 bytes
            unsigned a0, a1, a2, a3;
            ldsm4(a0, a1, a2, a3, qa_base + kcb);
#pragma unroll
            for (int p = 0; p < 4; p++) {
                unsigned b0, b1, b2, b3;
                ldsm4(b0, b1, b2, b3, ks_u + bfrag_off + p * PSTRIDE + kcb);
                mma8(s[2 * p][0], s[2 * p][1], s[2 * p][2], s[2 * p][3],
                     a0, a1, a2, a3, b0, b1);
                mma8(s[2 * p + 1][0], s[2 * p + 1][1], s[2 * p + 1][2], s[2 * p + 1][3],
                     a0, a1, a2, a3, b2, b3);
            }
        }

        // scale + mask in registers
        const int qq0 = qr + g;
        const int qq1 = qr + 8 + g;
#pragma unroll
        for (int j = 0; j < 8; j++) {
            int c0 = k0 + j * 8 + 2 * t;
            int c1 = c0 + 1;
            s[j][0] = (c0 > qq0 || c0 >= klen) ? -INFINITY : s[j][0] * 0.125f;
            s[j][1] = (c1 > qq0 || c1 >= klen) ? -INFINITY : s[j][1] * 0.125f;
            s[j][2] = (c0 > qq1 || c0 >= klen) ? -INFINITY : s[j][2] * 0.125f;
            s[j][3] = (c1 > qq1 || c1 >= klen) ? -INFINITY : s[j][3] * 0.125f;
        }

        // row max (registers + intra-quad shfl)
        float mt0 = -INFINITY, mt1 = -INFINITY;
#pragma unroll
        for (int j = 0; j < 8; j++) {
            mt0 = fmaxf(mt0, fmaxf(s[j][0], s[j][1]));
            mt1 = fmaxf(mt1, fmaxf(s[j][2], s[j][3]));
        }
        mt0 = fmaxf(mt0, __shfl_xor_sync(0xffffffffu, mt0, 1));
        mt0 = fmaxf(mt0, __shfl_xor_sync(0xffffffffu, mt0, 2));
        mt1 = fmaxf(mt1, __shfl_xor_sync(0xffffffffu, mt1, 1));
        mt1 = fmaxf(mt1, __shfl_xor_sync(0xffffffffu, mt1, 2));

        float mn0 = fmaxf(m0r, mt0);
        float mn1 = fmaxf(m1r, mt1);
        float alpha0, alpha1, sum0 = 0.0f, sum1 = 0.0f;

        if (mn0 == -INFINITY) {
            alpha0 = 1.0f;
#pragma unroll
            for (int j = 0; j < 8; j++) { s[j][0] = 0.0f; s[j][1] = 0.0f; }
        } else {
            alpha0 = (m0r == -INFINITY) ? 0.0f : __expf(m0r - mn0);
#pragma unroll
            for (int j = 0; j < 8; j++) {
                s[j][0] = __expf(s[j][0] - mn0);
                s[j][1] = __expf(s[j][1] - mn0);
                sum0 += s[j][0] + s[j][1];
            }
        }
        if (mn1 == -INFINITY) {
            alpha1 = 1.0f;
#pragma unroll
            for (int j = 0; j < 8; j++) { s[j][2] = 0.0f; s[j][3] = 0.0f; }
        } else {
            alpha1 = (m1r == -INFINITY) ? 0.0f : __expf(m1r - mn1);
#pragma unroll
            for (int j = 0; j < 8; j++) {
                s[j][2] = __expf(s[j][2] - mn1);
                s[j][3] = __expf(s[j][3] - mn1);
                sum1 += s[j][2] + s[j][3];
            }
        }
        sum0 += __shfl_xor_sync(0xffffffffu, sum0, 1);
        sum0 += __shfl_xor_sync(0xffffffffu, sum0, 2);
        sum1 += __shfl_xor_sync(0xffffffffu, sum1, 1);
        sum1 += __shfl_xor_sync(0xffffffffu, sum1, 2);
        l0 = l0 * alpha0 + sum0;  m0r = mn0;
        l1 = l1 * alpha1 + sum1;  m1r = mn1;

        // O *= alpha; round P to tf32 (rna) in place
#pragma unroll
        for (int j = 0; j < 8; j++) {
            acc[j][0] *= alpha0; acc[j][1] *= alpha0;
            acc[j][2] *= alpha1; acc[j][3] *= alpha1;
            s[j][0] = tf32f(s[j][0]); s[j][1] = tf32f(s[j][1]);
            s[j][2] = tf32f(s[j][2]); s[j][3] = tf32f(s[j][3]);
        }

        // PV: A-fragment built by intra-quad shuffles from s (C-layout).
        const int srcA = (lane & ~3) | (t >> 1);
        const int srcB = srcA + 2;
        const bool odd = (t & 1);
#pragma unroll
        for (int kb = 0; kb < 8; kb++) {
            float vA0 = __shfl_sync(0xffffffffu, s[kb][0], srcA);
            float vA1 = __shfl_sync(0xffffffffu, s[kb][1], srcA);
            float vA2 = __shfl_sync(0xffffffffu, s[kb][2], srcA);
            float vA3 = __shfl_sync(0xffffffffu, s[kb][3], srcA);
            float vB0 = __shfl_sync(0xffffffffu, s[kb][0], srcB);
            float vB1 = __shfl_sync(0xffffffffu, s[kb][1], srcB);
            float vB2 = __shfl_sync(0xffffffffu, s[kb][2], srcB);
            float vB3 = __shfl_sync(0xffffffffu, s[kb][3], srcB);
            unsigned a0 = __float_as_uint(odd ? vA1 : vA0);
            unsigned a1 = __float_as_uint(odd ? vA3 : vA2);
            unsigned a2 = __float_as_uint(odd ? vB1 : vB0);
            unsigned a3 = __float_as_uint(odd ? vB3 : vB2);
            const uint32_t kcb = (uint32_t)(kb * 32);
#pragma unroll
            for (int p = 0; p < 4; p++) {
                unsigned b0, b1, b2, b3;
                ldsm4(b0, b1, b2, b3, vt_u + bfrag_off + p * PSTRIDE + kcb);
                mma8(acc[2 * p][0], acc[2 * p][1], acc[2 * p][2], acc[2 * p][3],
                     a0, a1, a2, a3, b0, b1);
                mma8(acc[2 * p + 1][0], acc[2 * p + 1][1], acc[2 * p + 1][2], acc[2 * p + 1][3],
                     a0, a1, a2, a3, b2, b3);
            }
        }
    }

    // Epilogue: normalize, residual, query-padding override.
    float inv0 = (l0 > 0.0f) ? (1.0f / l0) : 0.0f;
    float inv1 = (l1 > 0.0f) ? (1.0f / l1) : 0.0f;
    const int qq0 = qr + g;
    const int qq1 = qr + 8 + g;
#pragma unroll
    for (int j = 0; j < 8; j++) {
        int c = j * 8 + 2 * t;
        {
            size_t oidx = (size_t)(b * SS + qq0) * DD + h * HD + c;
            float2 r2 = *(const float2*)&qin[oidx];
            float2 o = (qq0 >= qlen) ? r2
                     : make_float2(acc[j][0] * inv0 + r2.x, acc[j][1] * inv0 + r2.y);
            *(float2*)&out[oidx] = o;
        }
        {
            size_t oidx = (size_t)(b * SS + qq1) * DD + h * HD + c;
            float2 r2 = *(const float2*)&qin[oidx];
            float2 o = (qq1 >= qlen) ? r2
                     : make_float2(acc[j][2] * inv1 + r2.x, acc[j][3] * inv1 + r2.y);
            *(float2*)&out[oidx] = o;
        }
    }
}

// ---------------------------------------------------------------------------
extern "C" void kernel_launch(void* const* d_in, const int* in_sizes, int n_in,
                              void* d_out, int out_size) {
    const float* q  = (const float*)d_in[0];
    const float* k  = (const float*)d_in[1];
    const float* v  = (const float*)d_in[2];
    const float* Wq = (const float*)d_in[3];
    const float* bq = (const float*)d_in[4];
    const float* Wk = (const float*)d_in[5];
    const float* bk = (const float*)d_in[6];
    const float* Wv = (const float*)d_in[7];
    const float* bv = (const float*)d_in[8];
    const unsigned char* km = (const unsigned char*)d_in[9];
    const unsigned char* qm = (const unsigned char*)d_in[10];
    float* out = (float*)d_out;

    static bool attr_set = false;
    if (!attr_set) {
        cudaFuncSetAttribute(attn_kernel,
                             cudaFuncAttributeMaxDynamicSharedMemorySize,
                             ATTN_SMEM_FLOATS * (int)sizeof(float));
        cudaFuncSetAttribute(proj_kernel,
                             cudaFuncAttributeMaxDynamicSharedMemorySize,
                             PROJ_SMEM);
        attr_set = true;
    }

    dim3 pg(DD / 128, (BB * SS) / 128, 3);
    proj_kernel<<<pg, 256, PROJ_SMEM>>>(q, k, v, Wq, Wk, Wv, bq, bk, bv, km, qm);

    dim3 ag(SS / 128, HH, BB);
    attn_kernel<<<ag, 256, ATTN_SMEM_FLOATS * (int)sizeof(float)>>>(q, out);
}

// round 13
// speedup vs baseline: 1.1642x; 1.0429x over previous
#include <cuda_runtime.h>
#include <math.h>
#include <stdint.h>

#define BB 2
#define SS 2048
#define DD 1024
#define HH 16
#define HD 64

// Single dynamic-smem declaration shared by all kernels.
extern __shared__ char dynsmem[];

// Scratch: projected Q,K in [B,H,S,HD]; V transposed in [B,H,HD,S]
__device__ float g_Q[BB * HH * SS * HD];
__device__ float g_K[BB * HH * SS * HD];
__device__ float g_V[BB * HH * SS * HD];   // [B,H,HD,S] layout!
__device__ int g_klen[BB];
__device__ int g_qlen[BB];

// ---------------------------------------------------------------------------
// helpers
// ---------------------------------------------------------------------------
__device__ __forceinline__ uint32_t smem_u32(const void* p) {
    uint32_t a;
    asm("{ .reg .u64 t; cvta.to.shared.u64 t, %1; cvt.u32.u64 %0, t; }" : "=r"(a) : "l"(p));
    return a;
}
#define SWZ128(x) ((x) ^ (((x) >> 3) & 0x70))

__device__ __forceinline__ void cp16(uint32_t dst, const void* src) {
    asm volatile("cp.async.cg.shared.global [%0], [%1], 16;" :: "r"(dst), "l"(src) : "memory");
}
#define CP_COMMIT() asm volatile("cp.async.commit_group;" ::: "memory")
#define CP_WAIT0() asm volatile("cp.async.wait_group 0;" ::: "memory")
#define CP_WAIT1() asm volatile("cp.async.wait_group 1;" ::: "memory")

__device__ __forceinline__ unsigned tf32u(float x) {
    unsigned u; asm("cvt.rna.tf32.f32 %0, %1;" : "=r"(u) : "f"(x)); return u;
}
__device__ __forceinline__ float tf32f(float x) {
    return __uint_as_float(tf32u(x));
}
__device__ __forceinline__ void mma8(float& c0, float& c1, float& c2, float& c3,
                                     unsigned a0, unsigned a1, unsigned a2, unsigned a3,
                                     unsigned b0, unsigned b1) {
    asm volatile(
        "mma.sync.aligned.m16n8k8.row.col.f32.tf32.tf32.f32 "
        "{%0,%1,%2,%3},{%4,%5,%6,%7},{%8,%9},{%0,%1,%2,%3};"
        : "+f"(c0), "+f"(c1), "+f"(c2), "+f"(c3)
        : "r"(a0), "r"(a1), "r"(a2), "r"(a3), "r"(b0), "r"(b1));
}
// ldmatrix x4: one instruction loads 4 fragments.
__device__ __forceinline__ void ldsm4(unsigned& r0, unsigned& r1, unsigned& r2, unsigned& r3,
                                      uint32_t addr) {
    asm volatile("ldmatrix.sync.aligned.m8n8.x4.shared.b16 {%0,%1,%2,%3}, [%4];"
                 : "=r"(r0), "=r"(r1), "=r"(r2), "=r"(r3) : "r"(addr));
}

// ---------------------------------------------------------------------------
// Projection GEMM, tf32 mma.sync + ldmatrix. BM=128, BN=128, BK=32.
// 8 warps in 4(m)x2(n); warp tile 32x64. 2-stage cp.async double buffer.
// V epilogue: two-pass smem transpose -> coalesced [hd][s] float4 stores.
// CTA (0,0,0) additionally computes the mask lengths.
// ---------------------------------------------------------------------------
#define PSTAGE 32768         // A 16KB + B 16KB
#define PB_OFF 16384
#define PROJ_SMEM (2 * PSTAGE)
#define PPITCH 132           // V transpose staging pitch (132 mod 32 = 4 -> conflict-free)

__global__ __launch_bounds__(256, 2) void proj_kernel(
    const float* __restrict__ q, const float* __restrict__ k, const float* __restrict__ v,
    const float* __restrict__ Wq, const float* __restrict__ Wk, const float* __restrict__ Wv,
    const float* __restrict__ bq, const float* __restrict__ bk, const float* __restrict__ bv,
    const unsigned char* __restrict__ km, const unsigned char* __restrict__ qm) {
    char* smem = dynsmem;
    const uint32_t sb = smem_u32(smem);
    const int tid = threadIdx.x;
    const int lane = tid & 31;
    const int wid = tid >> 5;
    const int g = lane >> 2;
    const int t = lane & 3;
    const int wy = wid & 3;    // m band (32 rows)
    const int wx = wid >> 2;   // n half (64 cols)

    // --- fold mask-length computation into one CTA (hidden in the wave) ---
    __shared__ int cnt[4];
    if (blockIdx.x == 0 && blockIdx.y == 0 && blockIdx.z == 0) {
        if (tid < 4) cnt[tid] = 0;
        __syncthreads();
        int wk = (km[1] | km[2] | km[3]) ? 1 : 4;
        int wq = (qm[1] | qm[2] | qm[3]) ? 1 : 4;
#pragma unroll
        for (int b = 0; b < BB; b++) {
            int ck = 0, cq = 0;
            for (int i = tid; i < SS * wk; i += 256) ck += (km[(size_t)b * SS * wk + i] != 0);
            for (int i = tid; i < SS * wq; i += 256) cq += (qm[(size_t)b * SS * wq + i] != 0);
#pragma unroll
            for (int o = 16; o > 0; o >>= 1) {
                ck += __shfl_down_sync(0xffffffffu, ck, o);
                cq += __shfl_down_sync(0xffffffffu, cq, o);
            }
            if (lane == 0) { atomicAdd(&cnt[b], ck); atomicAdd(&cnt[2 + b], cq); }
        }
        __syncthreads();
        if (tid < 2) { g_klen[tid] = cnt[tid]; g_qlen[tid] = cnt[2 + tid]; }
    }

    const int which = blockIdx.z;
    const float* X = (which == 0) ? q : (which == 1) ? k : v;
    const float* W = (which == 0) ? Wq : (which == 1) ? Wk : Wv;
    const float* bias = (which == 0) ? bq : (which == 1) ? bk : bv;
    float* dst = (which == 0) ? g_Q : (which == 1) ? g_K : g_V;

    const int n0 = blockIdx.x * 128;
    const int m0 = blockIdx.y * 128;

    const int r0 = tid >> 3;
    const int cb = (tid & 7) * 16;

    const int row_sel = lane & 7;
    const int tl = lane >> 3;
    const uint32_t rowA0 = (uint32_t)((wy * 32 + (tl & 1) * 8 + row_sel) * 128);
    const uint32_t rowB0 = (uint32_t)((wx * 64 + (tl >> 1) * 8 + row_sel) * 128);

    float acc[2][8][4] = {};

    auto load_tile = [&](int kt, int stage) {
        const int kf = kt * 32 + (cb >> 2);
        const uint32_t abase = sb + stage * PSTAGE;
#pragma unroll
        for (int i = 0; i < 4; i++) {
            int r = r0 + 32 * i;
            uint32_t sw = SWZ128((uint32_t)(r * 128 + cb));
            cp16(abase + sw, X + (size_t)(m0 + r) * DD + kf);
            cp16(abase + PB_OFF + sw, W + (size_t)(n0 + r) * DD + kf);
        }
    };

    load_tile(0, 0); CP_COMMIT();
    load_tile(1, 1); CP_COMMIT();

    for (int kt = 0; kt < 32; kt++) {
        const int st = kt & 1;
        if (kt < 30) CP_WAIT1(); else CP_WAIT0();
        __syncthreads();

        const uint32_t au = sb + st * PSTAGE;
        const uint32_t bu = au + PB_OFF;
#pragma unroll
        for (int ks = 0; ks < 4; ks++) {
            const int kc = ks * 8;
            const uint32_t colA = (uint32_t)((kc + (tl >> 1) * 4) * 4);
            const uint32_t colB = (uint32_t)((kc + (tl & 1) * 4) * 4);
            unsigned a[2][4];
            ldsm4(a[0][0], a[0][1], a[0][2], a[0][3], au + SWZ128(rowA0 + colA));
            ldsm4(a[1][0], a[1][1], a[1][2], a[1][3], au + SWZ128(rowA0 + 16 * 128 + colA));
#pragma unroll
            for (int p = 0; p < 4; p++) {
                unsigned b0, b1, b2, b3;
                ldsm4(b0, b1, b2, b3, bu + SWZ128(rowB0 + (uint32_t)(p * 16 * 128) + colB));
                const int j0 = 2 * p, j1 = 2 * p + 1;
                mma8(acc[0][j0][0], acc[0][j0][1], acc[0][j0][2], acc[0][j0][3],
                     a[0][0], a[0][1], a[0][2], a[0][3], b0, b1);
                mma8(acc[1][j0][0], acc[1][j0][1], acc[1][j0][2], acc[1][j0][3],
                     a[1][0], a[1][1], a[1][2], a[1][3], b0, b1);
                mma8(acc[0][j1][0], acc[0][j1][1], acc[0][j1][2], acc[0][j1][3],
                     a[0][0], a[0][1], a[0][2], a[0][3], b2, b3);
                mma8(acc[1][j1][0], acc[1][j1][1], acc[1][j1][2], acc[1][j1][3],
                     a[1][0], a[1][1], a[1][2], a[1][3], b2, b3);
            }
        }
        __syncthreads();
        if (kt + 2 < 32) { load_tile(kt + 2, st); CP_COMMIT(); }
    }

    if (which == 2) {
        // V: stage transpose through smem; coalesced [hd][s] float4 stores.
        float* Vs = (float*)smem;   // [64][PPITCH] per pass
#pragma unroll
        for (int p = 0; p < 2; p++) {
            __syncthreads();
            if (wx == p) {
#pragma unroll
                for (int j = 0; j < 8; j++) {
                    int c = j * 8 + 2 * t;                 // n_local 0..62
#pragma unroll
                    for (int mi = 0; mi < 2; mi++) {
#pragma unroll
                        for (int half = 0; half < 2; half++) {
                            int m = wy * 32 + mi * 16 + half * 8 + g;
                            Vs[c * PPITCH + m] = acc[mi][j][half * 2 + 0];
                            Vs[(c + 1) * PPITCH + m] = acc[mi][j][half * 2 + 1];
                        }
                    }
                }
            }
            __syncthreads();
            const int hglob = blockIdx.x * 2 + p;
#pragma unroll
            for (int rr = 0; rr < 8; rr++) {
                int n_local = wid * 8 + rr;                // 0..63 = hd
                float bv = bias[n0 + p * 64 + n_local];
                float4 vv = *(float4*)&Vs[n_local * PPITCH + lane * 4];
                vv.x += bv; vv.y += bv; vv.z += bv; vv.w += bv;
                int m = m0 + lane * 4;
                int b = m >> 11;
                int s = m & (SS - 1);
                *(float4*)&dst[((size_t)((b * HH + hglob) * HD) + n_local) * SS + s] = vv;
            }
        }
    } else {
        // Q/K epilogue: bias + float2 stores in [B,H,S,HD].
#pragma unroll
        for (int j = 0; j < 8; j++) {
            const int cglob = n0 + wx * 64 + j * 8 + 2 * t;
            const int h = cglob >> 6;
            const int hd = cglob & 63;
            const float b0v = bias[cglob];
            const float b1v = bias[cglob + 1];
#pragma unroll
            for (int mi = 0; mi < 2; mi++) {
#pragma unroll
                for (int half = 0; half < 2; half++) {
                    int r = m0 + wy * 32 + mi * 16 + g + half * 8;
                    int b = r >> 11;
                    int s = r & (SS - 1);
                    *(float2*)&dst[((size_t)((b * HH + h) * SS) + s) * HD + hd] =
                        make_float2(acc[mi][j][half * 2 + 0] + b0v,
                                    acc[mi][j][half * 2 + 1] + b1v);
                }
            }
        }
    }
}

// ---------------------------------------------------------------------------
// Flash attention v5: BM=128, BN=64, warp owns 16 full rows.
// Q in smem pre-scaled by 0.125*log2e (exp2 softmax); register softmax with
// interior-tile mask skip; P->A via intra-quad shuffles (raw fp32 bits to
// MMA); ldmatrix fragments; cp.async double-buffered K/V. 2 CTAs/SM.
// ---------------------------------------------------------------------------
#define ALD 68
#define ATILE (64 * ALD)
#define QS_OFF 0
#define KS_OFF (128 * ALD)
#define VS_OFF (KS_OFF + 2 * ATILE)
#define ATTN_SMEM_FLOATS (128 * ALD + 4 * ATILE)
#define QSCALE 0.18033688f   // 0.125 * log2(e)

__global__ __launch_bounds__(256, 2) void attn_kernel(
    const float* __restrict__ qin, float* __restrict__ out) {
    float* smf = (float*)dynsmem;
    const uint32_t sb = smem_u32(dynsmem);

    const int qt = blockIdx.x;
    const int h  = blockIdx.y;
    const int b  = blockIdx.z;
    const int q0 = qt * 128;
    const int klen = g_klen[b];
    const int qlen = g_qlen[b];

    const int tid = threadIdx.x;
    const int lane = tid & 31;
    const int w = tid >> 5;
    const int g = lane >> 2;
    const int t = lane & 3;

    if (q0 >= qlen) {
#pragma unroll
        for (int i = 0; i < 8; i++) {
            int id = tid + 256 * i;
            int row = id >> 4;
            int cf = (id & 15) * 4;
            size_t oidx = (size_t)(b * SS + q0 + row) * DD + h * HD + cf;
            *(float4*)&out[oidx] = *(const float4*)&qin[oidx];
        }
        return;
    }

    const float* Qb = g_Q + (size_t)((b * HH + h) * SS) * HD;
    const float* Kb = g_K + (size_t)((b * HH + h) * SS) * HD;
    const float* Vb = g_V + (size_t)((b * HH + h) * HD) * SS;

    const int kend = min(klen, q0 + 128);
    const int nt = (kend + 63) >> 6;

    auto load_kv = [&](int ti, int st) {
        const int k0 = ti * 64;
        const uint32_t kbase = sb + (uint32_t)(KS_OFF + st * ATILE) * 4;
        const uint32_t vbase = sb + (uint32_t)(VS_OFF + st * ATILE) * 4;
#pragma unroll
        for (int i = 0; i < 4; i++) {
            int id = tid + 256 * i;
            int row = id >> 4;
            int cf = (id & 15) * 4;
            cp16(kbase + (uint32_t)(row * ALD + cf) * 4, Kb + (size_t)(k0 + row) * HD + cf);
            cp16(vbase + (uint32_t)(row * ALD + cf) * 4, Vb + (size_t)row * SS + k0 + cf);
        }
    };

    load_kv(0, 0); CP_COMMIT();

    // Q tile -> smem once, pre-scaled by 0.125*log2e, tf32-rounded.
#pragma unroll
    for (int i = 0; i < 8; i++) {
        int id = tid + 256 * i;
        int row = id >> 4;
        int cf = (id & 15) * 4;
        float4 a = *(const float4*)&Qb[(size_t)(q0 + row) * HD + cf];
        float* qs = smf + QS_OFF + row * ALD + cf;
        qs[0] = tf32f(a.x * QSCALE); qs[1] = tf32f(a.y * QSCALE);
        qs[2] = tf32f(a.z * QSCALE); qs[3] = tf32f(a.w * QSCALE);
    }

    const int qr = q0 + w * 16;

    const int row_sel = lane & 7;
    const int tl = lane >> 3;
    const uint32_t qa_base = sb + 4u * (uint32_t)(QS_OFF +
                             (w * 16 + (tl & 1) * 8 + row_sel) * ALD + (tl >> 1) * 4);
    const uint32_t bfrag_off = 4u * (uint32_t)(((tl >> 1) * 8 + row_sel) * ALD + (tl & 1) * 4);
    const uint32_t PSTRIDE = 4u * 16u * ALD;

    float m0r = -INFINITY, m1r = -INFINITY;
    float l0 = 0.0f, l1 = 0.0f;
    float acc[8][4] = {};

    for (int ti = 0; ti < nt; ti++) {
        const int k0 = ti * 64;
        const int st = ti & 1;
        __syncthreads();
        if (ti + 1 < nt) { load_kv(ti + 1, (ti + 1) & 1); CP_COMMIT(); CP_WAIT1(); }
        else CP_WAIT0();
        __syncthreads();

        const uint32_t ks_u = sb + 4u * (uint32_t)(KS_OFF + st * ATILE);
        const uint32_t vt_u = sb + 4u * (uint32_t)(VS_OFF + st * ATILE);

        // S = Q K^T (log2-domain, scale folded into Q)
        float s[8][4] = {};
#pragma unroll
        for (int kb = 0; kb < 8; kb++) {
            const uint32_t kcb = (uint32_t)(kb * 32);
            unsigned a0, a1, a2, a3;
            ldsm4(a0, a1, a2, a3, qa_base + kcb);
#pragma unroll
            for (int p = 0; p < 4; p++) {
                unsigned b0, b1, b2, b3;
                ldsm4(b0, b1, b2, b3, ks_u + bfrag_off + p * PSTRIDE + kcb);
                mma8(s[2 * p][0], s[2 * p][1], s[2 * p][2], s[2 * p][3],
                     a0, a1, a2, a3, b0, b1);
                mma8(s[2 * p + 1][0], s[2 * p + 1][1], s[2 * p + 1][2], s[2 * p + 1][3],
                     a0, a1, a2, a3, b2, b3);
            }
        }

        // mask only when the tile can touch causal edge or key padding
        const int qq0 = qr + g;
        const int qq1 = qr + 8 + g;
        if (k0 + 63 > qr || k0 + 64 > klen) {
#pragma unroll
            for (int j = 0; j < 8; j++) {
                int c0 = k0 + j * 8 + 2 * t;
                int c1 = c0 + 1;
                if (c0 > qq0 || c0 >= klen) s[j][0] = -INFINITY;
                if (c1 > qq0 || c1 >= klen) s[j][1] = -INFINITY;
                if (c0 > qq1 || c0 >= klen) s[j][2] = -INFINITY;
                if (c1 > qq1 || c1 >= klen) s[j][3] = -INFINITY;
            }
        }

        // row max
        float mt0 = -INFINITY, mt1 = -INFINITY;
#pragma unroll
        for (int j = 0; j < 8; j++) {
            mt0 = fmaxf(mt0, fmaxf(s[j][0], s[j][1]));
            mt1 = fmaxf(mt1, fmaxf(s[j][2], s[j][3]));
        }
        mt0 = fmaxf(mt0, __shfl_xor_sync(0xffffffffu, mt0, 1));
        mt0 = fmaxf(mt0, __shfl_xor_sync(0xffffffffu, mt0, 2));
        mt1 = fmaxf(mt1, __shfl_xor_sync(0xffffffffu, mt1, 1));
        mt1 = fmaxf(mt1, __shfl_xor_sync(0xffffffffu, mt1, 2));

        float mn0 = fmaxf(m0r, mt0);
        float mn1 = fmaxf(m1r, mt1);
        float alpha0, alpha1, sum0 = 0.0f, sum1 = 0.0f;

        if (mn0 == -INFINITY) {
            alpha0 = 1.0f;
#pragma unroll
            for (int j = 0; j < 8; j++) { s[j][0] = 0.0f; s[j][1] = 0.0f; }
        } else {
            alpha0 = (m0r == -INFINITY) ? 0.0f : exp2f(m0r - mn0);
#pragma unroll
            for (int j = 0; j < 8; j++) {
                s[j][0] = exp2f(s[j][0] - mn0);
                s[j][1] = exp2f(s[j][1] - mn0);
                sum0 += s[j][0] + s[j][1];
            }
        }
        if (mn1 == -INFINITY) {
            alpha1 = 1.0f;
#pragma unroll
            for (int j = 0; j < 8; j++) { s[j][2] = 0.0f; s[j][3] = 0.0f; }
        } else {
            alpha1 = (m1r == -INFINITY) ? 0.0f : exp2f(m1r - mn1);
#pragma unroll
            for (int j = 0; j < 8; j++) {
                s[j][2] = exp2f(s[j][2] - mn1);
                s[j][3] = exp2f(s[j][3] - mn1);
                sum1 += s[j][2] + s[j][3];
            }
        }
        sum0 += __shfl_xor_sync(0xffffffffu, sum0, 1);
        sum0 += __shfl_xor_sync(0xffffffffu, sum0, 2);
        sum1 += __shfl_xor_sync(0xffffffffu, sum1, 1);
        sum1 += __shfl_xor_sync(0xffffffffu, sum1, 2);
        l0 = l0 * alpha0 + sum0;  m0r = mn0;
        l1 = l1 * alpha1 + sum1;  m1r = mn1;

        // O *= alpha (P fed as raw fp32 bits; HW truncates to tf32)
#pragma unroll
        for (int j = 0; j < 8; j++) {
            acc[j][0] *= alpha0; acc[j][1] *= alpha0;
            acc[j][2] *= alpha1; acc[j][3] *= alpha1;
        }

        // PV: A-fragment built by intra-quad shuffles from s (C-layout).
        const int srcA = (lane & ~3) | (t >> 1);
        const int srcB = srcA + 2;
        const bool odd = (t & 1);
#pragma unroll
        for (int kb = 0; kb < 8; kb++) {
            float vA0 = __shfl_sync(0xffffffffu, s[kb][0], srcA);
            float vA1 = __shfl_sync(0xffffffffu, s[kb][1], srcA);
            float vA2 = __shfl_sync(0xffffffffu, s[kb][2], srcA);
            float vA3 = __shfl_sync(0xffffffffu, s[kb][3], srcA);
            float vB0 = __shfl_sync(0xffffffffu, s[kb][0], srcB);
            float vB1 = __shfl_sync(0xffffffffu, s[kb][1], srcB);
            float vB2 = __shfl_sync(0xffffffffu, s[kb][2], srcB);
            float vB3 = __shfl_sync(0xffffffffu, s[kb][3], srcB);
            unsigned a0 = __float_as_uint(odd ? vA1 : vA0);
            unsigned a1 = __float_as_uint(odd ? vA3 : vA2);
            unsigned a2 = __float_as_uint(odd ? vB1 : vB0);
            unsigned a3 = __float_as_uint(odd ? vB3 : vB2);
            const uint32_t kcb = (uint32_t)(kb * 32);
#pragma unroll
            for (int p = 0; p < 4; p++) {
                unsigned b0, b1, b2, b3;
                ldsm4(b0, b1, b2, b3, vt_u + bfrag_off + p * PSTRIDE + kcb);
                mma8(acc[2 * p][0], acc[2 * p][1], acc[2 * p][2], acc[2 * p][3],
                     a0, a1, a2, a3, b0, b1);
                mma8(acc[2 * p + 1][0], acc[2 * p + 1][1], acc[2 * p + 1][2], acc[2 * p + 1][3],
                     a0, a1, a2, a3, b2, b3);
            }
        }
    }

    // Epilogue: normalize, residual, query-padding override.
    float inv0 = (l0 > 0.0f) ? (1.0f / l0) : 0.0f;
    float inv1 = (l1 > 0.0f) ? (1.0f / l1) : 0.0f;
    const int qq0 = qr + g;
    const int qq1 = qr + 8 + g;
#pragma unroll
    for (int j = 0; j < 8; j++) {
        int c = j * 8 + 2 * t;
        {
            size_t oidx = (size_t)(b * SS + qq0) * DD + h * HD + c;
            float2 r2 = *(const float2*)&qin[oidx];
            float2 o = (qq0 >= qlen) ? r2
                     : make_float2(acc[j][0] * inv0 + r2.x, acc[j][1] * inv0 + r2.y);
            *(float2*)&out[oidx] = o;
        }
        {
            size_t oidx = (size_t)(b * SS + qq1) * DD + h * HD + c;
            float2 r2 = *(const float2*)&qin[oidx];
            float2 o = (qq1 >= qlen) ? r2
                     : make_float2(acc[j][2] * inv1 + r2.x, acc[j][3] * inv1 + r2.y);
            *(float2*)&out[oidx] = o;
        }
    }
}

// ---------------------------------------------------------------------------
extern "C" void kernel_launch(void* const* d_in, const int* in_sizes, int n_in,
                              void* d_out, int out_size) {
    const float* q  = (const float*)d_in[0];
    const float* k  = (const float*)d_in[1];
    const float* v  = (const float*)d_in[2];
    const float* Wq = (const float*)d_in[3];
    const float* bq = (const float*)d_in[4];
    const float* Wk = (const float*)d_in[5];
    const float* bk = (const float*)d_in[6];
    const float* Wv = (const float*)d_in[7];
    const float* bv = (const float*)d_in[8];
    const unsigned char* km = (const unsigned char*)d_in[9];
    const unsigned char* qm = (const unsigned char*)d_in[10];
    float* out = (float*)d_out;

    static bool attr_set = false;
    if (!attr_set) {
        cudaFuncSetAttribute(attn_kernel,
                             cudaFuncAttributeMaxDynamicSharedMemorySize,
                             ATTN_SMEM_FLOATS * (int)sizeof(float));
        cudaFuncSetAttribute(proj_kernel,
                             cudaFuncAttributeMaxDynamicSharedMemorySize,
                             PROJ_SMEM);
        attr_set = true;
    }

    dim3 pg(DD / 128, (BB * SS) / 128, 3);
    proj_kernel<<<pg, 256, PROJ_SMEM>>>(q, k, v, Wq, Wk, Wv, bq, bk, bv, km, qm);

    dim3 ag(SS / 128, HH, BB);
    attn_kernel<<<ag, 256, ATTN_SMEM_FLOATS * (int)sizeof(float)>>>(q, out);
}

// round 15
// speedup vs baseline: 1.4452x; 1.2414x over previous
#include <cuda_runtime.h>
#include <cuda_fp16.h>
#include <math.h>
#include <stdint.h>

#define BB 2
#define SS 2048
#define DD 1024
#define HH 16
#define HD 64

// Single dynamic-smem declaration shared by all kernels.
extern __shared__ char dynsmem[];

// Scratch (fp16): Q pre-scaled by 0.125*log2e, [B,H,S,HD]; K [B,H,S,HD];
// V transposed [B,H,HD,S].
__device__ __half g_Q[BB * HH * SS * HD];
__device__ __half g_K[BB * HH * SS * HD];
__device__ __half g_V[BB * HH * SS * HD];
__device__ int g_klen[BB];
__device__ int g_qlen[BB];

#define QSCALE 0.18033688f   // 0.125 * log2(e)

// ---------------------------------------------------------------------------
// helpers
// ---------------------------------------------------------------------------
__device__ __forceinline__ uint32_t smem_u32(const void* p) {
    uint32_t a;
    asm("{ .reg .u64 t; cvta.to.shared.u64 t, %1; cvt.u32.u64 %0, t; }" : "=r"(a) : "l"(p));
    return a;
}
#define SWZ128(x) ((x) ^ (((x) >> 3) & 0x70))

__device__ __forceinline__ void cp16(uint32_t dst, const void* src) {
    asm volatile("cp.async.cg.shared.global [%0], [%1], 16;" :: "r"(dst), "l"(src) : "memory");
}
#define CP_COMMIT() asm volatile("cp.async.commit_group;" ::: "memory")
#define CP_WAIT0() asm volatile("cp.async.wait_group 0;" ::: "memory")
#define CP_WAIT1() asm volatile("cp.async.wait_group 1;" ::: "memory")

__device__ __forceinline__ void mma8(float& c0, float& c1, float& c2, float& c3,
                                     unsigned a0, unsigned a1, unsigned a2, unsigned a3,
                                     unsigned b0, unsigned b1) {
    asm volatile(
        "mma.sync.aligned.m16n8k8.row.col.f32.tf32.tf32.f32 "
        "{%0,%1,%2,%3},{%4,%5,%6,%7},{%8,%9},{%0,%1,%2,%3};"
        : "+f"(c0), "+f"(c1), "+f"(c2), "+f"(c3)
        : "r"(a0), "r"(a1), "r"(a2), "r"(a3), "r"(b0), "r"(b1));
}
__device__ __forceinline__ void mma16(float& c0, float& c1, float& c2, float& c3,
                                      unsigned a0, unsigned a1, unsigned a2, unsigned a3,
                                      unsigned b0, unsigned b1) {
    asm volatile(
        "mma.sync.aligned.m16n8k16.row.col.f32.f16.f16.f32 "
        "{%0,%1,%2,%3},{%4,%5,%6,%7},{%8,%9},{%0,%1,%2,%3};"
        : "+f"(c0), "+f"(c1), "+f"(c2), "+f"(c3)
        : "r"(a0), "r"(a1), "r"(a2), "r"(a3), "r"(b0), "r"(b1));
}
__device__ __forceinline__ void ldsm4(unsigned& r0, unsigned& r1, unsigned& r2, unsigned& r3,
                                      uint32_t addr) {
    asm volatile("ldmatrix.sync.aligned.m8n8.x4.shared.b16 {%0,%1,%2,%3}, [%4];"
                 : "=r"(r0), "=r"(r1), "=r"(r2), "=r"(r3) : "r"(addr));
}
// pack (lo=x, hi=y) into one fp16x2 register
__device__ __forceinline__ unsigned packh2(float x, float y) {
    unsigned u;
    asm("cvt.rn.f16x2.f32 %0, %1, %2;" : "=r"(u) : "f"(y), "f"(x));
    return u;
}

// ---------------------------------------------------------------------------
// Projection GEMM (tf32 mma.sync + ldmatrix), fp16 output. BM=128, BN=128.
// V epilogue: smem transpose -> coalesced [hd][s] fp16 stores.
// CTA (0,0,0) folds the mask-length computation.
// ---------------------------------------------------------------------------
#define PSTAGE 32768
#define PB_OFF 16384
#define PROJ_SMEM (2 * PSTAGE)
#define PPITCH 132

__global__ __launch_bounds__(256, 2) void proj_kernel(
    const float* __restrict__ q, const float* __restrict__ k, const float* __restrict__ v,
    const float* __restrict__ Wq, const float* __restrict__ Wk, const float* __restrict__ Wv,
    const float* __restrict__ bq, const float* __restrict__ bk, const float* __restrict__ bv,
    const unsigned char* __restrict__ km, const unsigned char* __restrict__ qm) {
    char* smem = dynsmem;
    const uint32_t sb = smem_u32(smem);
    const int tid = threadIdx.x;
    const int lane = tid & 31;
    const int wid = tid >> 5;
    const int g = lane >> 2;
    const int t = lane & 3;
    const int wy = wid & 3;
    const int wx = wid >> 2;

    __shared__ int cnt[4];
    if (blockIdx.x == 0 && blockIdx.y == 0 && blockIdx.z == 0) {
        if (tid < 4) cnt[tid] = 0;
        __syncthreads();
        int wk = (km[1] | km[2] | km[3]) ? 1 : 4;
        int wq = (qm[1] | qm[2] | qm[3]) ? 1 : 4;
#pragma unroll
        for (int b = 0; b < BB; b++) {
            int ck = 0, cq = 0;
            for (int i = tid; i < SS * wk; i += 256) ck += (km[(size_t)b * SS * wk + i] != 0);
            for (int i = tid; i < SS * wq; i += 256) cq += (qm[(size_t)b * SS * wq + i] != 0);
#pragma unroll
            for (int o = 16; o > 0; o >>= 1) {
                ck += __shfl_down_sync(0xffffffffu, ck, o);
                cq += __shfl_down_sync(0xffffffffu, cq, o);
            }
            if (lane == 0) { atomicAdd(&cnt[b], ck); atomicAdd(&cnt[2 + b], cq); }
        }
        __syncthreads();
        if (tid < 2) { g_klen[tid] = cnt[tid]; g_qlen[tid] = cnt[2 + tid]; }
    }

    const int which = blockIdx.z;
    const float* X = (which == 0) ? q : (which == 1) ? k : v;
    const float* W = (which == 0) ? Wq : (which == 1) ? Wk : Wv;
    const float* bias = (which == 0) ? bq : (which == 1) ? bk : bv;
    __half* dst = (which == 0) ? g_Q : (which == 1) ? g_K : g_V;

    const int n0 = blockIdx.x * 128;
    const int m0 = blockIdx.y * 128;

    const int r0 = tid >> 3;
    const int cb = (tid & 7) * 16;

    const int row_sel = lane & 7;
    const int tl = lane >> 3;
    const uint32_t rowA0 = (uint32_t)((wy * 32 + (tl & 1) * 8 + row_sel) * 128);
    const uint32_t rowB0 = (uint32_t)((wx * 64 + (tl >> 1) * 8 + row_sel) * 128);

    float acc[2][8][4] = {};

    auto load_tile = [&](int kt, int stage) {
        const int kf = kt * 32 + (cb >> 2);
        const uint32_t abase = sb + stage * PSTAGE;
#pragma unroll
        for (int i = 0; i < 4; i++) {
            int r = r0 + 32 * i;
            uint32_t sw = SWZ128((uint32_t)(r * 128 + cb));
            cp16(abase + sw, X + (size_t)(m0 + r) * DD + kf);
            cp16(abase + PB_OFF + sw, W + (size_t)(n0 + r) * DD + kf);
        }
    };

    load_tile(0, 0); CP_COMMIT();
    load_tile(1, 1); CP_COMMIT();

    for (int kt = 0; kt < 32; kt++) {
        const int st = kt & 1;
        if (kt < 30) CP_WAIT1(); else CP_WAIT0();
        __syncthreads();

        const uint32_t au = sb + st * PSTAGE;
        const uint32_t bu = au + PB_OFF;
#pragma unroll
        for (int ks = 0; ks < 4; ks++) {
            const int kc = ks * 8;
            const uint32_t colA = (uint32_t)((kc + (tl >> 1) * 4) * 4);
            const uint32_t colB = (uint32_t)((kc + (tl & 1) * 4) * 4);
            unsigned a[2][4];
            ldsm4(a[0][0], a[0][1], a[0][2], a[0][3], au + SWZ128(rowA0 + colA));
            ldsm4(a[1][0], a[1][1], a[1][2], a[1][3], au + SWZ128(rowA0 + 16 * 128 + colA));
#pragma unroll
            for (int p = 0; p < 4; p++) {
                unsigned b0, b1, b2, b3;
                ldsm4(b0, b1, b2, b3, bu + SWZ128(rowB0 + (uint32_t)(p * 16 * 128) + colB));
                const int j0 = 2 * p, j1 = 2 * p + 1;
                mma8(acc[0][j0][0], acc[0][j0][1], acc[0][j0][2], acc[0][j0][3],
                     a[0][0], a[0][1], a[0][2], a[0][3], b0, b1);
                mma8(acc[1][j0][0], acc[1][j0][1], acc[1][j0][2], acc[1][j0][3],
                     a[1][0], a[1][1], a[1][2], a[1][3], b0, b1);
                mma8(acc[0][j1][0], acc[0][j1][1], acc[0][j1][2], acc[0][j1][3],
                     a[0][0], a[0][1], a[0][2], a[0][3], b2, b3);
                mma8(acc[1][j1][0], acc[1][j1][1], acc[1][j1][2], acc[1][j1][3],
                     a[1][0], a[1][1], a[1][2], a[1][3], b2, b3);
            }
        }
        __syncthreads();
        if (kt + 2 < 32) { load_tile(kt + 2, st); CP_COMMIT(); }
    }

    if (which == 2) {
        // V: smem transpose -> coalesced [hd][s] fp16 stores.
        float* Vs = (float*)smem;
#pragma unroll
        for (int p = 0; p < 2; p++) {
            __syncthreads();
            if (wx == p) {
#pragma unroll
                for (int j = 0; j < 8; j++) {
                    int c = j * 8 + 2 * t;
#pragma unroll
                    for (int mi = 0; mi < 2; mi++) {
#pragma unroll
                        for (int half = 0; half < 2; half++) {
                            int m = wy * 32 + mi * 16 + half * 8 + g;
                            Vs[c * PPITCH + m] = acc[mi][j][half * 2 + 0];
                            Vs[(c + 1) * PPITCH + m] = acc[mi][j][half * 2 + 1];
                        }
                    }
                }
            }
            __syncthreads();
            const int hglob = blockIdx.x * 2 + p;
#pragma unroll
            for (int rr = 0; rr < 8; rr++) {
                int n_local = wid * 8 + rr;
                float bv = bias[n0 + p * 64 + n_local];
                float4 vv = *(float4*)&Vs[n_local * PPITCH + lane * 4];
                __half2 h0 = __floats2half2_rn(vv.x + bv, vv.y + bv);
                __half2 h1 = __floats2half2_rn(vv.z + bv, vv.w + bv);
                int m = m0 + lane * 4;
                int b = m >> 11;
                int s = m & (SS - 1);
                uint2 pk = make_uint2(*(unsigned*)&h0, *(unsigned*)&h1);
                *(uint2*)&dst[((size_t)((b * HH + hglob) * HD) + n_local) * SS + s] = pk;
            }
        }
    } else {
        const float sc = (which == 0) ? QSCALE : 1.0f;
#pragma unroll
        for (int j = 0; j < 8; j++) {
            const int cglob = n0 + wx * 64 + j * 8 + 2 * t;
            const int h = cglob >> 6;
            const int hd = cglob & 63;
            const float b0v = bias[cglob];
            const float b1v = bias[cglob + 1];
#pragma unroll
            for (int mi = 0; mi < 2; mi++) {
#pragma unroll
                for (int half = 0; half < 2; half++) {
                    int r = m0 + wy * 32 + mi * 16 + g + half * 8;
                    int b = r >> 11;
                    int s = r & (SS - 1);
                    __half2 hv = __floats2half2_rn((acc[mi][j][half * 2 + 0] + b0v) * sc,
                                                   (acc[mi][j][half * 2 + 1] + b1v) * sc);
                    *(__half2*)&dst[((size_t)((b * HH + h) * SS) + s) * HD + hd] = hv;
                }
            }
        }
    }
}

// ---------------------------------------------------------------------------
// Flash attention v6: fp16 m16n8k16 MMA. BM=128, BN=64, warp owns 16 rows.
// QK C-fragment == PV A-fragment (no shuffles). Register softmax (exp2,
// interior mask skip). cp.async double-buffered fp16 K/V. 2 CTAs/SM.
// ---------------------------------------------------------------------------
#define KLD 72                          // fp16 elems per row (144B, 9x16B: conflict-free)
#define KTILE_B (64 * KLD * 2)          // 9216 bytes per K or V tile
#define QS_B 0
#define KS_B (128 * KLD * 2)            // Q tile 18432 bytes
#define VS_B (KS_B + 2 * KTILE_B)
#define ATTN_SMEM_BYTES (KS_B + 4 * KTILE_B)   // 55296

__global__ __launch_bounds__(256, 2) void attn_kernel(
    const float* __restrict__ qin, float* __restrict__ out) {
    const uint32_t sb = smem_u32(dynsmem);

    const int qt = blockIdx.x;
    const int h  = blockIdx.y;
    const int b  = blockIdx.z;
    const int q0 = qt * 128;
    const int klen = g_klen[b];
    const int qlen = g_qlen[b];

    const int tid = threadIdx.x;
    const int lane = tid & 31;
    const int w = tid >> 5;
    const int g = lane >> 2;
    const int t = lane & 3;

    if (q0 >= qlen) {
#pragma unroll
        for (int i = 0; i < 8; i++) {
            int id = tid + 256 * i;
            int row = id >> 4;
            int cf = (id & 15) * 4;
            size_t oidx = (size_t)(b * SS + q0 + row) * DD + h * HD + cf;
            *(float4*)&out[oidx] = *(const float4*)&qin[oidx];
        }
        return;
    }

    const __half* Qb = g_Q + (size_t)((b * HH + h) * SS) * HD;
    const __half* Kb = g_K + (size_t)((b * HH + h) * SS) * HD;
    const __half* Vb = g_V + (size_t)((b * HH + h) * HD) * SS;

    const int kend = min(klen, q0 + 128);
    const int nt = (kend + 63) >> 6;

    // K/V tile: 64 rows x 64 fp16 = 512 16B-chunks = 2 iters x 256 threads.
    auto load_kv = [&](int ti, int st) {
        const int k0 = ti * 64;
        const uint32_t kbase = sb + KS_B + (uint32_t)st * KTILE_B;
        const uint32_t vbase = sb + VS_B + (uint32_t)st * KTILE_B;
#pragma unroll
        for (int i = 0; i < 2; i++) {
            int id = tid + 256 * i;
            int row = id >> 3;          // 0..63
            int cf = (id & 7) * 8;      // fp16 col 0..56
            cp16(kbase + (uint32_t)(row * KLD + cf) * 2, Kb + (size_t)(k0 + row) * HD + cf);
            cp16(vbase + (uint32_t)(row * KLD + cf) * 2, Vb + (size_t)row * SS + k0 + cf);
        }
    };

    load_kv(0, 0); CP_COMMIT();

    // Q tile (fp16, already scaled): 128 rows x 64 = 1024 chunks = 4 iters.
#pragma unroll
    for (int i = 0; i < 4; i++) {
        int id = tid + 256 * i;
        int row = id >> 3;
        int cf = (id & 7) * 8;
        cp16(sb + QS_B + (uint32_t)(row * KLD + cf) * 2, Qb + (size_t)(q0 + row) * HD + cf);
    }
    CP_COMMIT();   // Q gets its own group -> first CP_WAIT1 retires KV0 + Q

    const int qr = q0 + w * 16;

    const int row_sel = lane & 7;
    const int tl = lane >> 3;
    // A (Q): tiles (row-half = tl&1, k-half = tl>>1), 8 fp16 per k-half
    const uint32_t qa_base = sb + QS_B +
        2u * (uint32_t)((w * 16 + (tl & 1) * 8 + row_sel) * KLD + (tl >> 1) * 8);
    // B (K/V): tiles (n-parity = tl>>1, k-half = tl&1)
    const uint32_t bfrag_off =
        2u * (uint32_t)(((tl >> 1) * 8 + row_sel) * KLD + (tl & 1) * 8);
    const uint32_t PSTRIDE = 2u * 16u * KLD;   // bytes per n-pair (16 rows)

    float m0r = -INFINITY, m1r = -INFINITY;
    float l0 = 0.0f, l1 = 0.0f;
    float acc[8][4] = {};

    for (int ti = 0; ti < nt; ti++) {
        const int k0 = ti * 64;
        const int st = ti & 1;
        __syncthreads();
        if (ti + 1 < nt) { load_kv(ti + 1, (ti + 1) & 1); CP_COMMIT(); CP_WAIT1(); }
        else CP_WAIT0();
        __syncthreads();

        const uint32_t ks_u = sb + KS_B + (uint32_t)st * KTILE_B;
        const uint32_t vt_u = sb + VS_B + (uint32_t)st * KTILE_B;

        // S = Q K^T (log2 domain; scale folded into stored Q)
        float s[8][4] = {};
#pragma unroll
        for (int kb = 0; kb < 4; kb++) {
            const uint32_t kcb = (uint32_t)(kb * 32);   // 16 fp16 = 32B per k-step
            unsigned a0, a1, a2, a3;
            ldsm4(a0, a1, a2, a3, qa_base + kcb);
#pragma unroll
            for (int p = 0; p < 4; p++) {
                unsigned b0, b1, b2, b3;
                ldsm4(b0, b1, b2, b3, ks_u + bfrag_off + p * PSTRIDE + kcb);
                mma16(s[2 * p][0], s[2 * p][1], s[2 * p][2], s[2 * p][3],
                      a0, a1, a2, a3, b0, b1);
                mma16(s[2 * p + 1][0], s[2 * p + 1][1], s[2 * p + 1][2], s[2 * p + 1][3],
                      a0, a1, a2, a3, b2, b3);
            }
        }

        const int qq0 = qr + g;
        const int qq1 = qr + 8 + g;
        if (k0 + 63 > qr || k0 + 64 > klen) {
#pragma unroll
            for (int j = 0; j < 8; j++) {
                int c0 = k0 + j * 8 + 2 * t;
                int c1 = c0 + 1;
                if (c0 > qq0 || c0 >= klen) s[j][0] = -INFINITY;
                if (c1 > qq0 || c1 >= klen) s[j][1] = -INFINITY;
                if (c0 > qq1 || c0 >= klen) s[j][2] = -INFINITY;
                if (c1 > qq1 || c1 >= klen) s[j][3] = -INFINITY;
            }
        }

        float mt0 = -INFINITY, mt1 = -INFINITY;
#pragma unroll
        for (int j = 0; j < 8; j++) {
            mt0 = fmaxf(mt0, fmaxf(s[j][0], s[j][1]));
            mt1 = fmaxf(mt1, fmaxf(s[j][2], s[j][3]));
        }
        mt0 = fmaxf(mt0, __shfl_xor_sync(0xffffffffu, mt0, 1));
        mt0 = fmaxf(mt0, __shfl_xor_sync(0xffffffffu, mt0, 2));
        mt1 = fmaxf(mt1, __shfl_xor_sync(0xffffffffu, mt1, 1));
        mt1 = fmaxf(mt1, __shfl_xor_sync(0xffffffffu, mt1, 2));

        float mn0 = fmaxf(m0r, mt0);
        float mn1 = fmaxf(m1r, mt1);
        float alpha0, alpha1, sum0 = 0.0f, sum1 = 0.0f;

        if (mn0 == -INFINITY) {
            alpha0 = 1.0f;
#pragma unroll
            for (int j = 0; j < 8; j++) { s[j][0] = 0.0f; s[j][1] = 0.0f; }
        } else {
            alpha0 = (m0r == -INFINITY) ? 0.0f : exp2f(m0r - mn0);
#pragma unroll
            for (int j = 0; j < 8; j++) {
                s[j][0] = exp2f(s[j][0] - mn0);
                s[j][1] = exp2f(s[j][1] - mn0);
                sum0 += s[j][0] + s[j][1];
            }
        }
        if (mn1 == -INFINITY) {
            alpha1 = 1.0f;
#pragma unroll
            for (int j = 0; j < 8; j++) { s[j][2] = 0.0f; s[j][3] = 0.0f; }
        } else {
            alpha1 = (m1r == -INFINITY) ? 0.0f : exp2f(m1r - mn1);
#pragma unroll
            for (int j = 0; j < 8; j++) {
                s[j][2] = exp2f(s[j][2] - mn1);
                s[j][3] = exp2f(s[j][3] - mn1);
                sum1 += s[j][2] + s[j][3];
            }
        }
        sum0 += __shfl_xor_sync(0xffffffffu, sum0, 1);
        sum0 += __shfl_xor_sync(0xffffffffu, sum0, 2);
        sum1 += __shfl_xor_sync(0xffffffffu, sum1, 1);
        sum1 += __shfl_xor_sync(0xffffffffu, sum1, 2);
        l0 = l0 * alpha0 + sum0;  m0r = mn0;
        l1 = l1 * alpha1 + sum1;  m1r = mn1;

#pragma unroll
        for (int j = 0; j < 8; j++) {
            acc[j][0] *= alpha0; acc[j][1] *= alpha0;
            acc[j][2] *= alpha1; acc[j][3] *= alpha1;
        }

        // PV: QK C-fragment IS the fp16 A-fragment (pack only, no shuffles).
#pragma unroll
        for (int kb = 0; kb < 4; kb++) {
            unsigned a0 = packh2(s[2 * kb][0], s[2 * kb][1]);
            unsigned a1 = packh2(s[2 * kb][2], s[2 * kb][3]);
            unsigned a2 = packh2(s[2 * kb + 1][0], s[2 * kb + 1][1]);
            unsigned a3 = packh2(s[2 * kb + 1][2], s[2 * kb + 1][3]);
            const uint32_t kcb = (uint32_t)(kb * 32);
#pragma unroll
            for (int p = 0; p < 4; p++) {
                unsigned b0, b1, b2, b3;
                ldsm4(b0, b1, b2, b3, vt_u + bfrag_off + p * PSTRIDE + kcb);
                mma16(acc[2 * p][0], acc[2 * p][1], acc[2 * p][2], acc[2 * p][3],
                      a0, a1, a2, a3, b0, b1);
                mma16(acc[2 * p + 1][0], acc[2 * p + 1][1], acc[2 * p + 1][2], acc[2 * p + 1][3],
                      a0, a1, a2, a3, b2, b3);
            }
        }
    }

    // Epilogue: normalize, residual, query-padding override.
    float inv0 = (l0 > 0.0f) ? (1.0f / l0) : 0.0f;
    float inv1 = (l1 > 0.0f) ? (1.0f / l1) : 0.0f;
    const int qq0 = qr + g;
    const int qq1 = qr + 8 + g;
#pragma unroll
    for (int j = 0; j < 8; j++) {
        int c = j * 8 + 2 * t;
        {
            size_t oidx = (size_t)(b * SS + qq0) * DD + h * HD + c;
            float2 r2 = *(const float2*)&qin[oidx];
            float2 o = (qq0 >= qlen) ? r2
                     : make_float2(acc[j][0] * inv0 + r2.x, acc[j][1] * inv0 + r2.y);
            *(float2*)&out[oidx] = o;
        }
        {
            size_t oidx = (size_t)(b * SS + qq1) * DD + h * HD + c;
            float2 r2 = *(const float2*)&qin[oidx];
            float2 o = (qq1 >= qlen) ? r2
                     : make_float2(acc[j][2] * inv1 + r2.x, acc[j][3] * inv1 + r2.y);
            *(float2*)&out[oidx] = o;
        }
    }
}

// ---------------------------------------------------------------------------
extern "C" void kernel_launch(void* const* d_in, const int* in_sizes, int n_in,
                              void* d_out, int out_size) {
    const float* q  = (const float*)d_in[0];
    const float* k  = (const float*)d_in[1];
    const float* v  = (const float*)d_in[2];
    const float* Wq = (const float*)d_in[3];
    const float* bq = (const float*)d_in[4];
    const float* Wk = (const float*)d_in[5];
    const float* bk = (const float*)d_in[6];
    const float* Wv = (const float*)d_in[7];
    const float* bv = (const float*)d_in[8];
    const unsigned char* km = (const unsigned char*)d_in[9];
    const unsigned char* qm = (const unsigned char*)d_in[10];
    float* out = (float*)d_out;

    static bool attr_set = false;
    if (!attr_set) {
        cudaFuncSetAttribute(attn_kernel,
                             cudaFuncAttributeMaxDynamicSharedMemorySize,
                             ATTN_SMEM_BYTES);
        cudaFuncSetAttribute(proj_kernel,
                             cudaFuncAttributeMaxDynamicSharedMemorySize,
                             PROJ_SMEM);
        attr_set = true;
    }

    dim3 pg(DD / 128, (BB * SS) / 128, 3);
    proj_kernel<<<pg, 256, PROJ_SMEM>>>(q, k, v, Wq, Wk, Wv, bq, bk, bv, km, qm);

    dim3 ag(SS / 128, HH, BB);
    attn_kernel<<<ag, 256, ATTN_SMEM_BYTES>>>(q, out);
}

// round 16
// speedup vs baseline: 2.0108x; 1.3914x over previous
#include <cuda_runtime.h>
#include <cuda_fp16.h>
#include <math.h>
#include <stdint.h>

#define BB 2
#define SS 2048
#define DD 1024
#define HH 16
#define HD 64
#define NX (BB * SS * DD)
#define NW (DD * DD)

// Single dynamic-smem declaration shared by all kernels.
extern __shared__ char dynsmem[];

// fp16 copies of the fp32 inputs (filled by cvt_kernel each launch)
__device__ __half g_hX[3 * NX];
__device__ __half g_hW[3 * NW];

// Scratch (fp16): Q pre-scaled by 0.125*log2e, [B,H,S,HD]; K [B,H,S,HD];
// V transposed [B,H,HD,S].
__device__ __half g_Q[BB * HH * SS * HD];
__device__ __half g_K[BB * HH * SS * HD];
__device__ __half g_V[BB * HH * SS * HD];
__device__ int g_klen[BB];
__device__ int g_qlen[BB];

#define QSCALE 0.18033688f   // 0.125 * log2(e)

// ---------------------------------------------------------------------------
// helpers
// ---------------------------------------------------------------------------
__device__ __forceinline__ uint32_t smem_u32(const void* p) {
    uint32_t a;
    asm("{ .reg .u64 t; cvta.to.shared.u64 t, %1; cvt.u32.u64 %0, t; }" : "=r"(a) : "l"(p));
    return a;
}
#define SWZ128(x) ((x) ^ (((x) >> 3) & 0x70))

__device__ __forceinline__ void cp16(uint32_t dst, const void* src) {
    asm volatile("cp.async.cg.shared.global [%0], [%1], 16;" :: "r"(dst), "l"(src) : "memory");
}
#define CP_COMMIT() asm volatile("cp.async.commit_group;" ::: "memory")
#define CP_WAIT0() asm volatile("cp.async.wait_group 0;" ::: "memory")
#define CP_WAIT1() asm volatile("cp.async.wait_group 1;" ::: "memory")

__device__ __forceinline__ void mma16(float& c0, float& c1, float& c2, float& c3,
                                      unsigned a0, unsigned a1, unsigned a2, unsigned a3,
                                      unsigned b0, unsigned b1) {
    asm volatile(
        "mma.sync.aligned.m16n8k16.row.col.f32.f16.f16.f32 "
        "{%0,%1,%2,%3},{%4,%5,%6,%7},{%8,%9},{%0,%1,%2,%3};"
        : "+f"(c0), "+f"(c1), "+f"(c2), "+f"(c3)
        : "r"(a0), "r"(a1), "r"(a2), "r"(a3), "r"(b0), "r"(b1));
}
__device__ __forceinline__ void ldsm4(unsigned& r0, unsigned& r1, unsigned& r2, unsigned& r3,
                                      uint32_t addr) {
    asm volatile("ldmatrix.sync.aligned.m8n8.x4.shared.b16 {%0,%1,%2,%3}, [%4];"
                 : "=r"(r0), "=r"(r1), "=r"(r2), "=r"(r3) : "r"(addr));
}
__device__ __forceinline__ unsigned packh2(float x, float y) {
    unsigned u;
    asm("cvt.rn.f16x2.f32 %0, %1, %2;" : "=r"(u) : "f"(y), "f"(x));
    return u;
}

// ---------------------------------------------------------------------------
// fp32 -> fp16 conversion of the six inputs. 8 elems/thread, vectorized.
// blockIdx.y: 0..2 -> q,k,v (NX each); 3..5 -> Wq,Wk,Wv (NW each).
// ---------------------------------------------------------------------------
__global__ __launch_bounds__(256) void cvt_kernel(
    const float* __restrict__ q, const float* __restrict__ k, const float* __restrict__ v,
    const float* __restrict__ Wq, const float* __restrict__ Wk, const float* __restrict__ Wv) {
    const int which = blockIdx.y;
    const float* src;
    __half* dst;
    int n;
    if (which < 3) {
        src = (which == 0) ? q : (which == 1) ? k : v;
        dst = g_hX + (size_t)which * NX;
        n = NX;
    } else {
        src = (which == 3) ? Wq : (which == 4) ? Wk : Wv;
        dst = g_hW + (size_t)(which - 3) * NW;
        n = NW;
    }
    int base = (blockIdx.x * 256 + threadIdx.x) * 8;
    if (base >= n) return;
    float4 a = *(const float4*)&src[base];
    float4 c = *(const float4*)&src[base + 4];
    uint4 o;
    o.x = packh2(a.x, a.y);
    o.y = packh2(a.z, a.w);
    o.z = packh2(c.x, c.y);
    o.w = packh2(c.z, c.w);
    *(uint4*)&dst[base] = o;
}

// ---------------------------------------------------------------------------
// Projection GEMM, fp16 m16n8k16 + ldmatrix. BM=128, BN=128, BK=64.
// 8 warps in 4(m)x2(n); warp tile 32x64. 2-stage cp.async double buffer.
// Rows are 64 fp16 = 128B -> same SW128 swizzle as before.
// V epilogue: smem transpose -> coalesced [hd][s] fp16 stores.
// CTA (0,0,0) folds the mask-length computation.
// ---------------------------------------------------------------------------
#define PSTAGE 32768         // A 16KB + B 16KB
#define PB_OFF 16384
#define PROJ_SMEM (2 * PSTAGE)
#define PPITCH 132
#define KTILES 16

__global__ __launch_bounds__(256, 2) void proj_kernel(
    const float* __restrict__ bq, const float* __restrict__ bk, const float* __restrict__ bv,
    const unsigned char* __restrict__ km, const unsigned char* __restrict__ qm) {
    char* smem = dynsmem;
    const uint32_t sb = smem_u32(smem);
    const int tid = threadIdx.x;
    const int lane = tid & 31;
    const int wid = tid >> 5;
    const int g = lane >> 2;
    const int t = lane & 3;
    const int wy = wid & 3;
    const int wx = wid >> 2;

    __shared__ int cnt[4];
    if (blockIdx.x == 0 && blockIdx.y == 0 && blockIdx.z == 0) {
        if (tid < 4) cnt[tid] = 0;
        __syncthreads();
        int wk = (km[1] | km[2] | km[3]) ? 1 : 4;
        int wq = (qm[1] | qm[2] | qm[3]) ? 1 : 4;
#pragma unroll
        for (int b = 0; b < BB; b++) {
            int ck = 0, cq = 0;
            for (int i = tid; i < SS * wk; i += 256) ck += (km[(size_t)b * SS * wk + i] != 0);
            for (int i = tid; i < SS * wq; i += 256) cq += (qm[(size_t)b * SS * wq + i] != 0);
#pragma unroll
            for (int o = 16; o > 0; o >>= 1) {
                ck += __shfl_down_sync(0xffffffffu, ck, o);
                cq += __shfl_down_sync(0xffffffffu, cq, o);
            }
            if (lane == 0) { atomicAdd(&cnt[b], ck); atomicAdd(&cnt[2 + b], cq); }
        }
        __syncthreads();
        if (tid < 2) { g_klen[tid] = cnt[tid]; g_qlen[tid] = cnt[2 + tid]; }
    }

    const int which = blockIdx.z;
    const __half* X = g_hX + (size_t)which * NX;
    const __half* W = g_hW + (size_t)which * NW;
    const float* bias = (which == 0) ? bq : (which == 1) ? bk : bv;
    __half* dst = (which == 0) ? g_Q : (which == 1) ? g_K : g_V;

    const int n0 = blockIdx.x * 128;
    const int m0 = blockIdx.y * 128;

    const int r0 = tid >> 3;          // 0..31, +32 per i
    const int cb = (tid & 7) * 16;    // byte col within 128B row
    const int cf16 = (tid & 7) * 8;   // fp16 col

    const int row_sel = lane & 7;
    const int tl = lane >> 3;
    // A: row-half = tl&1, k-half = tl>>1 (16B)
    const uint32_t rowA0 = (uint32_t)((wy * 32 + (tl & 1) * 8 + row_sel) * 128);
    const uint32_t colA_t = (uint32_t)((tl >> 1) * 16);
    // B: n-parity = tl>>1, k-half = tl&1
    const uint32_t rowB0 = (uint32_t)((wx * 64 + (tl >> 1) * 8 + row_sel) * 128);
    const uint32_t colB_t = (uint32_t)((tl & 1) * 16);

    float acc[2][8][4] = {};

    auto load_tile = [&](int kt, int stage) {
        const int kf = kt * 64 + cf16;
        const uint32_t abase = sb + stage * PSTAGE;
#pragma unroll
        for (int i = 0; i < 4; i++) {
            int r = r0 + 32 * i;
            uint32_t sw = SWZ128((uint32_t)(r * 128 + cb));
            cp16(abase + sw, X + (size_t)(m0 + r) * DD + kf);
            cp16(abase + PB_OFF + sw, W + (size_t)(n0 + r) * DD + kf);
        }
    };

    load_tile(0, 0); CP_COMMIT();
    load_tile(1, 1); CP_COMMIT();

    for (int kt = 0; kt < KTILES; kt++) {
        const int st = kt & 1;
        if (kt < KTILES - 2) CP_WAIT1(); else CP_WAIT0();
        __syncthreads();

        const uint32_t au = sb + st * PSTAGE;
        const uint32_t bu = au + PB_OFF;
#pragma unroll
        for (int ks = 0; ks < 4; ks++) {
            const uint32_t kcb = (uint32_t)(ks * 32);   // 16 fp16 = 32B per k-step
            unsigned a[2][4];
            ldsm4(a[0][0], a[0][1], a[0][2], a[0][3], au + SWZ128(rowA0 + kcb + colA_t));
            ldsm4(a[1][0], a[1][1], a[1][2], a[1][3],
                  au + SWZ128(rowA0 + 16 * 128 + kcb + colA_t));
#pragma unroll
            for (int p = 0; p < 4; p++) {
                unsigned b0, b1, b2, b3;
                ldsm4(b0, b1, b2, b3,
                      bu + SWZ128(rowB0 + (uint32_t)(p * 16 * 128) + kcb + colB_t));
                const int j0 = 2 * p, j1 = 2 * p + 1;
                mma16(acc[0][j0][0], acc[0][j0][1], acc[0][j0][2], acc[0][j0][3],
                      a[0][0], a[0][1], a[0][2], a[0][3], b0, b1);
                mma16(acc[1][j0][0], acc[1][j0][1], acc[1][j0][2], acc[1][j0][3],
                      a[1][0], a[1][1], a[1][2], a[1][3], b0, b1);
                mma16(acc[0][j1][0], acc[0][j1][1], acc[0][j1][2], acc[0][j1][3],
                      a[0][0], a[0][1], a[0][2], a[0][3], b2, b3);
                mma16(acc[1][j1][0], acc[1][j1][1], acc[1][j1][2], acc[1][j1][3],
                      a[1][0], a[1][1], a[1][2], a[1][3], b2, b3);
            }
        }
        __syncthreads();
        if (kt + 2 < KTILES) { load_tile(kt + 2, st); CP_COMMIT(); }
    }

    if (which == 2) {
        // V: smem transpose -> coalesced [hd][s] fp16 stores.
        float* Vs = (float*)smem;
#pragma unroll
        for (int p = 0; p < 2; p++) {
            __syncthreads();
            if (wx == p) {
#pragma unroll
                for (int j = 0; j < 8; j++) {
                    int c = j * 8 + 2 * t;
#pragma unroll
                    for (int mi = 0; mi < 2; mi++) {
#pragma unroll
                        for (int half = 0; half < 2; half++) {
                            int m = wy * 32 + mi * 16 + half * 8 + g;
                            Vs[c * PPITCH + m] = acc[mi][j][half * 2 + 0];
                            Vs[(c + 1) * PPITCH + m] = acc[mi][j][half * 2 + 1];
                        }
                    }
                }
            }
            __syncthreads();
            const int hglob = blockIdx.x * 2 + p;
#pragma unroll
            for (int rr = 0; rr < 8; rr++) {
                int n_local = wid * 8 + rr;
                float bv = bias[n0 + p * 64 + n_local];
                float4 vv = *(float4*)&Vs[n_local * PPITCH + lane * 4];
                __half2 h0 = __floats2half2_rn(vv.x + bv, vv.y + bv);
                __half2 h1 = __floats2half2_rn(vv.z + bv, vv.w + bv);
                int m = m0 + lane * 4;
                int b = m >> 11;
                int s = m & (SS - 1);
                uint2 pk = make_uint2(*(unsigned*)&h0, *(unsigned*)&h1);
                *(uint2*)&dst[((size_t)((b * HH + hglob) * HD) + n_local) * SS + s] = pk;
            }
        }
    } else {
        const float sc = (which == 0) ? QSCALE : 1.0f;
#pragma unroll
        for (int j = 0; j < 8; j++) {
            const int cglob = n0 + wx * 64 + j * 8 + 2 * t;
            const int h = cglob >> 6;
            const int hd = cglob & 63;
            const float b0v = bias[cglob];
            const float b1v = bias[cglob + 1];
#pragma unroll
            for (int mi = 0; mi < 2; mi++) {
#pragma unroll
                for (int half = 0; half < 2; half++) {
                    int r = m0 + wy * 32 + mi * 16 + g + half * 8;
                    int b = r >> 11;
                    int s = r & (SS - 1);
                    __half2 hv = __floats2half2_rn((acc[mi][j][half * 2 + 0] + b0v) * sc,
                                                   (acc[mi][j][half * 2 + 1] + b1v) * sc);
                    *(__half2*)&dst[((size_t)((b * HH + h) * SS) + s) * HD + hd] = hv;
                }
            }
        }
    }
}

// ---------------------------------------------------------------------------
// Flash attention v6 (round-15 proven): fp16 m16n8k16, BM=128, BN=64,
// warp owns 16 rows, QK-C == PV-A fragment identity, register softmax.
// ---------------------------------------------------------------------------
#define KLD 72
#define KTILE_B (64 * KLD * 2)
#define QS_B 0
#define KS_B (128 * KLD * 2)
#define VS_B (KS_B + 2 * KTILE_B)
#define ATTN_SMEM_BYTES (KS_B + 4 * KTILE_B)

__global__ __launch_bounds__(256, 2) void attn_kernel(
    const float* __restrict__ qin, float* __restrict__ out) {
    const uint32_t sb = smem_u32(dynsmem);

    const int qt = blockIdx.x;
    const int h  = blockIdx.y;
    const int b  = blockIdx.z;
    const int q0 = qt * 128;
    const int klen = g_klen[b];
    const int qlen = g_qlen[b];

    const int tid = threadIdx.x;
    const int lane = tid & 31;
    const int w = tid >> 5;
    const int g = lane >> 2;
    const int t = lane & 3;

    if (q0 >= qlen) {
#pragma unroll
        for (int i = 0; i < 8; i++) {
            int id = tid + 256 * i;
            int row = id >> 4;
            int cf = (id & 15) * 4;
            size_t oidx = (size_t)(b * SS + q0 + row) * DD + h * HD + cf;
            *(float4*)&out[oidx] = *(const float4*)&qin[oidx];
        }
        return;
    }

    const __half* Qb = g_Q + (size_t)((b * HH + h) * SS) * HD;
    const __half* Kb = g_K + (size_t)((b * HH + h) * SS) * HD;
    const __half* Vb = g_V + (size_t)((b * HH + h) * HD) * SS;

    const int kend = min(klen, q0 + 128);
    const int nt = (kend + 63) >> 6;

    auto load_kv = [&](int ti, int st) {
        const int k0 = ti * 64;
        const uint32_t kbase = sb + KS_B + (uint32_t)st * KTILE_B;
        const uint32_t vbase = sb + VS_B + (uint32_t)st * KTILE_B;
#pragma unroll
        for (int i = 0; i < 2; i++) {
            int id = tid + 256 * i;
            int row = id >> 3;
            int cf = (id & 7) * 8;
            cp16(kbase + (uint32_t)(row * KLD + cf) * 2, Kb + (size_t)(k0 + row) * HD + cf);
            cp16(vbase + (uint32_t)(row * KLD + cf) * 2, Vb + (size_t)row * SS + k0 + cf);
        }
    };

    load_kv(0, 0); CP_COMMIT();

#pragma unroll
    for (int i = 0; i < 4; i++) {
        int id = tid + 256 * i;
        int row = id >> 3;
        int cf = (id & 7) * 8;
        cp16(sb + QS_B + (uint32_t)(row * KLD + cf) * 2, Qb + (size_t)(q0 + row) * HD + cf);
    }
    CP_COMMIT();   // Q gets its own group

    const int qr = q0 + w * 16;

    const int row_sel = lane & 7;
    const int tl = lane >> 3;
    const uint32_t qa_base = sb + QS_B +
        2u * (uint32_t)((w * 16 + (tl & 1) * 8 + row_sel) * KLD + (tl >> 1) * 8);
    const uint32_t bfrag_off =
        2u * (uint32_t)(((tl >> 1) * 8 + row_sel) * KLD + (tl & 1) * 8);
    const uint32_t PSTRIDE = 2u * 16u * KLD;

    float m0r = -INFINITY, m1r = -INFINITY;
    float l0 = 0.0f, l1 = 0.0f;
    float acc[8][4] = {};

    for (int ti = 0; ti < nt; ti++) {
        const int k0 = ti * 64;
        const int st = ti & 1;
        __syncthreads();
        if (ti + 1 < nt) { load_kv(ti + 1, (ti + 1) & 1); CP_COMMIT(); CP_WAIT1(); }
        else CP_WAIT0();
        __syncthreads();

        const uint32_t ks_u = sb + KS_B + (uint32_t)st * KTILE_B;
        const uint32_t vt_u = sb + VS_B + (uint32_t)st * KTILE_B;

        float s[8][4] = {};
#pragma unroll
        for (int kb = 0; kb < 4; kb++) {
            const uint32_t kcb = (uint32_t)(kb * 32);
            unsigned a0, a1, a2, a3;
            ldsm4(a0, a1, a2, a3, qa_base + kcb);
#pragma unroll
            for (int p = 0; p < 4; p++) {
                unsigned b0, b1, b2, b3;
                ldsm4(b0, b1, b2, b3, ks_u + bfrag_off + p * PSTRIDE + kcb);
                mma16(s[2 * p][0], s[2 * p][1], s[2 * p][2], s[2 * p][3],
                      a0, a1, a2, a3, b0, b1);
                mma16(s[2 * p + 1][0], s[2 * p + 1][1], s[2 * p + 1][2], s[2 * p + 1][3],
                      a0, a1, a2, a3, b2, b3);
            }
        }

        const int qq0 = qr + g;
        const int qq1 = qr + 8 + g;
        if (k0 + 63 > qr || k0 + 64 > klen) {
#pragma unroll
            for (int j = 0; j < 8; j++) {
                int c0 = k0 + j * 8 + 2 * t;
                int c1 = c0 + 1;
                if (c0 > qq0 || c0 >= klen) s[j][0] = -INFINITY;
                if (c1 > qq0 || c1 >= klen) s[j][1] = -INFINITY;
                if (c0 > qq1 || c0 >= klen) s[j][2] = -INFINITY;
                if (c1 > qq1 || c1 >= klen) s[j][3] = -INFINITY;
            }
        }

        float mt0 = -INFINITY, mt1 = -INFINITY;
#pragma unroll
        for (int j = 0; j < 8; j++) {
            mt0 = fmaxf(mt0, fmaxf(s[j][0], s[j][1]));
            mt1 = fmaxf(mt1, fmaxf(s[j][2], s[j][3]));
        }
        mt0 = fmaxf(mt0, __shfl_xor_sync(0xffffffffu, mt0, 1));
        mt0 = fmaxf(mt0, __shfl_xor_sync(0xffffffffu, mt0, 2));
        mt1 = fmaxf(mt1, __shfl_xor_sync(0xffffffffu, mt1, 1));
        mt1 = fmaxf(mt1, __shfl_xor_sync(0xffffffffu, mt1, 2));

        float mn0 = fmaxf(m0r, mt0);
        float mn1 = fmaxf(m1r, mt1);
        float alpha0, alpha1, sum0 = 0.0f, sum1 = 0.0f;

        if (mn0 == -INFINITY) {
            alpha0 = 1.0f;
#pragma unroll
            for (int j = 0; j < 8; j++) { s[j][0] = 0.0f; s[j][1] = 0.0f; }
        } else {
            alpha0 = (m0r == -INFINITY) ? 0.0f : exp2f(m0r - mn0);
#pragma unroll
            for (int j = 0; j < 8; j++) {
                s[j][0] = exp2f(s[j][0] - mn0);
                s[j][1] = exp2f(s[j][1] - mn0);
                sum0 += s[j][0] + s[j][1];
            }
        }
        if (mn1 == -INFINITY) {
            alpha1 = 1.0f;
#pragma unroll
            for (int j = 0; j < 8; j++) { s[j][2] = 0.0f; s[j][3] = 0.0f; }
        } else {
            alpha1 = (m1r == -INFINITY) ? 0.0f : exp2f(m1r - mn1);
#pragma unroll
            for (int j = 0; j < 8; j++) {
                s[j][2] = exp2f(s[j][2] - mn1);
                s[j][3] = exp2f(s[j][3] - mn1);
                sum1 += s[j][2] + s[j][3];
            }
        }
        sum0 += __shfl_xor_sync(0xffffffffu, sum0, 1);
        sum0 += __shfl_xor_sync(0xffffffffu, sum0, 2);
        sum1 += __shfl_xor_sync(0xffffffffu, sum1, 1);
        sum1 += __shfl_xor_sync(0xffffffffu, sum1, 2);
        l0 = l0 * alpha0 + sum0;  m0r = mn0;
        l1 = l1 * alpha1 + sum1;  m1r = mn1;

#pragma unroll
        for (int j = 0; j < 8; j++) {
            acc[j][0] *= alpha0; acc[j][1] *= alpha0;
            acc[j][2] *= alpha1; acc[j][3] *= alpha1;
        }

#pragma unroll
        for (int kb = 0; kb < 4; kb++) {
            unsigned a0 = packh2(s[2 * kb][0], s[2 * kb][1]);
            unsigned a1 = packh2(s[2 * kb][2], s[2 * kb][3]);
            unsigned a2 = packh2(s[2 * kb + 1][0], s[2 * kb + 1][1]);
            unsigned a3 = packh2(s[2 * kb + 1][2], s[2 * kb + 1][3]);
            const uint32_t kcb = (uint32_t)(kb * 32);
#pragma unroll
            for (int p = 0; p < 4; p++) {
                unsigned b0, b1, b2, b3;
                ldsm4(b0, b1, b2, b3, vt_u + bfrag_off + p * PSTRIDE + kcb);
                mma16(acc[2 * p][0], acc[2 * p][1], acc[2 * p][2], acc[2 * p][3],
                      a0, a1, a2, a3, b0, b1);
                mma16(acc[2 * p + 1][0], acc[2 * p + 1][1], acc[2 * p + 1][2], acc[2 * p + 1][3],
                      a0, a1, a2, a3, b2, b3);
            }
        }
    }

    float inv0 = (l0 > 0.0f) ? (1.0f / l0) : 0.0f;
    float inv1 = (l1 > 0.0f) ? (1.0f / l1) : 0.0f;
    const int qq0 = qr + g;
    const int qq1 = qr + 8 + g;
#pragma unroll
    for (int j = 0; j < 8; j++) {
        int c = j * 8 + 2 * t;
        {
            size_t oidx = (size_t)(b * SS + qq0) * DD + h * HD + c;
            float2 r2 = *(const float2*)&qin[oidx];
            float2 o = (qq0 >= qlen) ? r2
                     : make_float2(acc[j][0] * inv0 + r2.x, acc[j][1] * inv0 + r2.y);
            *(float2*)&out[oidx] = o;
        }
        {
            size_t oidx = (size_t)(b * SS + qq1) * DD + h * HD + c;
            float2 r2 = *(const float2*)&qin[oidx];
            float2 o = (qq1 >= qlen) ? r2
                     : make_float2(acc[j][2] * inv1 + r2.x, acc[j][3] * inv1 + r2.y);
            *(float2*)&out[oidx] = o;
        }
    }
}

// ---------------------------------------------------------------------------
extern "C" void kernel_launch(void* const* d_in, const int* in_sizes, int n_in,
                              void* d_out, int out_size) {
    const float* q  = (const float*)d_in[0];
    const float* k  = (const float*)d_in[1];
    const float* v  = (const float*)d_in[2];
    const float* Wq = (const float*)d_in[3];
    const float* bq = (const float*)d_in[4];
    const float* Wk = (const float*)d_in[5];
    const float* bk = (const float*)d_in[6];
    const float* Wv = (const float*)d_in[7];
    const float* bv = (const float*)d_in[8];
    const unsigned char* km = (const unsigned char*)d_in[9];
    const unsigned char* qm = (const unsigned char*)d_in[10];
    float* out = (float*)d_out;

    static bool attr_set = false;
    if (!attr_set) {
        cudaFuncSetAttribute(attn_kernel,
                             cudaFuncAttributeMaxDynamicSharedMemorySize,
                             ATTN_SMEM_BYTES);
        cudaFuncSetAttribute(proj_kernel,
                             cudaFuncAttributeMaxDynamicSharedMemorySize,
                             PROJ_SMEM);
        attr_set = true;
    }

    dim3 cg(NX / 8 / 256, 6);
    cvt_kernel<<<cg, 256>>>(q, k, v, Wq, Wk, Wv);

    dim3 pg(DD / 128, (BB * SS) / 128, 3);
    proj_kernel<<<pg, 256, PROJ_SMEM>>>(bq, bk, bv, km, qm);

    dim3 ag(SS / 128, HH, BB);
    attn_kernel<<<ag, 256, ATTN_SMEM_BYTES>>>(q, out);
}

// round 17
// speedup vs baseline: 2.0112x; 1.0002x over previous
#include <cuda_runtime.h>
#include <cuda_fp16.h>
#include <math.h>
#include <stdint.h>

#define BB 2
#define SS 2048
#define DD 1024
#define HH 16
#define HD 64
#define NX (BB * SS * DD)
#define NW (DD * DD)

// Single dynamic-smem declaration shared by all kernels.
extern __shared__ char dynsmem[];

// fp16 copies of the fp32 inputs (filled by cvt_kernel each launch)
__device__ __half g_hX[3 * NX];
__device__ __half g_hW[3 * NW];

// Scratch (fp16): Q pre-scaled by 0.125*log2e, [B,H,S,HD]; K [B,H,S,HD];
// V transposed [B,H,HD,S].
__device__ __half g_Q[BB * HH * SS * HD];
__device__ __half g_K[BB * HH * SS * HD];
__device__ __half g_V[BB * HH * SS * HD];
__device__ int g_klen[BB];
__device__ int g_qlen[BB];

#define QSCALE 0.18033688f   // 0.125 * log2(e)

// ---------------------------------------------------------------------------
// helpers
// ---------------------------------------------------------------------------
__device__ __forceinline__ uint32_t smem_u32(const void* p) {
    uint32_t a;
    asm("{ .reg .u64 t; cvta.to.shared.u64 t, %1; cvt.u32.u64 %0, t; }" : "=r"(a) : "l"(p));
    return a;
}
#define SWZ128(x) ((x) ^ (((x) >> 3) & 0x70))

__device__ __forceinline__ void cp16(uint32_t dst, const void* src) {
    asm volatile("cp.async.cg.shared.global [%0], [%1], 16;" :: "r"(dst), "l"(src) : "memory");
}
#define CP_COMMIT() asm volatile("cp.async.commit_group;" ::: "memory")
#define CP_WAIT0() asm volatile("cp.async.wait_group 0;" ::: "memory")
#define CP_WAIT1() asm volatile("cp.async.wait_group 1;" ::: "memory")

__device__ __forceinline__ void mma16(float& c0, float& c1, float& c2, float& c3,
                                      unsigned a0, unsigned a1, unsigned a2, unsigned a3,
                                      unsigned b0, unsigned b1) {
    asm volatile(
        "mma.sync.aligned.m16n8k16.row.col.f32.f16.f16.f32 "
        "{%0,%1,%2,%3},{%4,%5,%6,%7},{%8,%9},{%0,%1,%2,%3};"
        : "+f"(c0), "+f"(c1), "+f"(c2), "+f"(c3)
        : "r"(a0), "r"(a1), "r"(a2), "r"(a3), "r"(b0), "r"(b1));
}
__device__ __forceinline__ void ldsm4(unsigned& r0, unsigned& r1, unsigned& r2, unsigned& r3,
                                      uint32_t addr) {
    asm volatile("ldmatrix.sync.aligned.m8n8.x4.shared.b16 {%0,%1,%2,%3}, [%4];"
                 : "=r"(r0), "=r"(r1), "=r"(r2), "=r"(r3) : "r"(addr));
}
__device__ __forceinline__ unsigned packh2(float x, float y) {
    unsigned u;
    asm("cvt.rn.f16x2.f32 %0, %1, %2;" : "=r"(u) : "f"(y), "f"(x));
    return u;
}

// ---------------------------------------------------------------------------
// fp32 -> fp16 conversion of the six inputs.
// ---------------------------------------------------------------------------
__global__ __launch_bounds__(256) void cvt_kernel(
    const float* __restrict__ q, const float* __restrict__ k, const float* __restrict__ v,
    const float* __restrict__ Wq, const float* __restrict__ Wk, const float* __restrict__ Wv) {
    const int which = blockIdx.y;
    const float* src;
    __half* dst;
    int n;
    if (which < 3) {
        src = (which == 0) ? q : (which == 1) ? k : v;
        dst = g_hX + (size_t)which * NX;
        n = NX;
    } else {
        src = (which == 3) ? Wq : (which == 4) ? Wk : Wv;
        dst = g_hW + (size_t)(which - 3) * NW;
        n = NW;
    }
    int base = (blockIdx.x * 256 + threadIdx.x) * 8;
    if (base >= n) return;
    float4 a = *(const float4*)&src[base];
    float4 c = *(const float4*)&src[base + 4];
    uint4 o;
    o.x = packh2(a.x, a.y);
    o.y = packh2(a.z, a.w);
    o.z = packh2(c.x, c.y);
    o.w = packh2(c.z, c.w);
    *(uint4*)&dst[base] = o;
}

// ---------------------------------------------------------------------------
// Projection GEMM, fp16 m16n8k16 + ldmatrix. BM=256, BN=128, BK=64.
// 512 threads, 16 warps in 8(m)x2(n); warp tile 32x64 (identical per-warp
// structure to the proven BM=128 version; W L2 traffic halved).
// 2-stage cp.async double buffer. V epilogue: smem transpose.
// CTA (0,0,0) folds the mask-length computation.
// ---------------------------------------------------------------------------
#define PSTAGE 49152         // A 32KB + B 16KB
#define PB_OFF 32768
#define PROJ_SMEM (2 * PSTAGE)
#define PPITCH 260           // 260 mod 32 = 4 -> conflict-free (same as 132)
#define KTILES 16

__global__ __launch_bounds__(512, 1) void proj_kernel(
    const float* __restrict__ bq, const float* __restrict__ bk, const float* __restrict__ bv,
    const unsigned char* __restrict__ km, const unsigned char* __restrict__ qm) {
    char* smem = dynsmem;
    const uint32_t sb = smem_u32(smem);
    const int tid = threadIdx.x;
    const int lane = tid & 31;
    const int wid = tid >> 5;     // 0..15
    const int g = lane >> 2;
    const int t = lane & 3;
    const int wy = wid & 7;       // m band (32 rows), 0..7
    const int wx = wid >> 3;      // n half (64 cols), 0..1

    __shared__ int cnt[4];
    if (blockIdx.x == 0 && blockIdx.y == 0 && blockIdx.z == 0) {
        if (tid < 4) cnt[tid] = 0;
        __syncthreads();
        int wk = (km[1] | km[2] | km[3]) ? 1 : 4;
        int wq = (qm[1] | qm[2] | qm[3]) ? 1 : 4;
#pragma unroll
        for (int b = 0; b < BB; b++) {
            int ck = 0, cq = 0;
            for (int i = tid; i < SS * wk; i += 512) ck += (km[(size_t)b * SS * wk + i] != 0);
            for (int i = tid; i < SS * wq; i += 512) cq += (qm[(size_t)b * SS * wq + i] != 0);
#pragma unroll
            for (int o = 16; o > 0; o >>= 1) {
                ck += __shfl_down_sync(0xffffffffu, ck, o);
                cq += __shfl_down_sync(0xffffffffu, cq, o);
            }
            if (lane == 0) { atomicAdd(&cnt[b], ck); atomicAdd(&cnt[2 + b], cq); }
        }
        __syncthreads();
        if (tid < 2) { g_klen[tid] = cnt[tid]; g_qlen[tid] = cnt[2 + tid]; }
    }

    const int which = blockIdx.z;
    const __half* X = g_hX + (size_t)which * NX;
    const __half* W = g_hW + (size_t)which * NW;
    const float* bias = (which == 0) ? bq : (which == 1) ? bk : bv;
    __half* dst = (which == 0) ? g_Q : (which == 1) ? g_K : g_V;

    const int n0 = blockIdx.x * 128;
    const int m0 = blockIdx.y * 256;

    const int r0 = tid >> 3;          // 0..63
    const int cb = (tid & 7) * 16;    // byte col within 128B row
    const int cf16 = (tid & 7) * 8;   // fp16 col

    const int row_sel = lane & 7;
    const int tl = lane >> 3;
    const uint32_t rowA0 = (uint32_t)((wy * 32 + (tl & 1) * 8 + row_sel) * 128);
    const uint32_t colA_t = (uint32_t)((tl >> 1) * 16);
    const uint32_t rowB0 = (uint32_t)((wx * 64 + (tl >> 1) * 8 + row_sel) * 128);
    const uint32_t colB_t = (uint32_t)((tl & 1) * 16);

    float acc[2][8][4] = {};

    auto load_tile = [&](int kt, int stage) {
        const int kf = kt * 64 + cf16;
        const uint32_t abase = sb + stage * PSTAGE;
        // A: 256 rows (4 passes of 64 rows)
#pragma unroll
        for (int i = 0; i < 4; i++) {
            int r = r0 + 64 * i;
            cp16(abase + SWZ128((uint32_t)(r * 128 + cb)), X + (size_t)(m0 + r) * DD + kf);
        }
        // B: 128 rows (2 passes)
#pragma unroll
        for (int i = 0; i < 2; i++) {
            int r = r0 + 64 * i;
            cp16(abase + PB_OFF + SWZ128((uint32_t)(r * 128 + cb)),
                 W + (size_t)(n0 + r) * DD + kf);
        }
    };

    load_tile(0, 0); CP_COMMIT();
    load_tile(1, 1); CP_COMMIT();

    for (int kt = 0; kt < KTILES; kt++) {
        const int st = kt & 1;
        if (kt < KTILES - 2) CP_WAIT1(); else CP_WAIT0();
        __syncthreads();

        const uint32_t au = sb + st * PSTAGE;
        const uint32_t bu = au + PB_OFF;
#pragma unroll
        for (int ks = 0; ks < 4; ks++) {
            const uint32_t kcb = (uint32_t)(ks * 32);
            unsigned a[2][4];
            ldsm4(a[0][0], a[0][1], a[0][2], a[0][3], au + SWZ128(rowA0 + kcb + colA_t));
            ldsm4(a[1][0], a[1][1], a[1][2], a[1][3],
                  au + SWZ128(rowA0 + 16 * 128 + kcb + colA_t));
#pragma unroll
            for (int p = 0; p < 4; p++) {
                unsigned b0, b1, b2, b3;
                ldsm4(b0, b1, b2, b3,
                      bu + SWZ128(rowB0 + (uint32_t)(p * 16 * 128) + kcb + colB_t));
                const int j0 = 2 * p, j1 = 2 * p + 1;
                mma16(acc[0][j0][0], acc[0][j0][1], acc[0][j0][2], acc[0][j0][3],
                      a[0][0], a[0][1], a[0][2], a[0][3], b0, b1);
                mma16(acc[1][j0][0], acc[1][j0][1], acc[1][j0][2], acc[1][j0][3],
                      a[1][0], a[1][1], a[1][2], a[1][3], b0, b1);
                mma16(acc[0][j1][0], acc[0][j1][1], acc[0][j1][2], acc[0][j1][3],
                      a[0][0], a[0][1], a[0][2], a[0][3], b2, b3);
                mma16(acc[1][j1][0], acc[1][j1][1], acc[1][j1][2], acc[1][j1][3],
                      a[1][0], a[1][1], a[1][2], a[1][3], b2, b3);
            }
        }
        __syncthreads();
        if (kt + 2 < KTILES) { load_tile(kt + 2, st); CP_COMMIT(); }
    }

    if (which == 2) {
        // V: smem transpose -> coalesced [hd][s] fp16 stores.
        // Stage: Vs[64][PPITCH] covering m = 0..255 per n-half pass.
        float* Vs = (float*)smem;
#pragma unroll
        for (int p = 0; p < 2; p++) {
            __syncthreads();
            if (wx == p) {
#pragma unroll
                for (int j = 0; j < 8; j++) {
                    int c = j * 8 + 2 * t;
#pragma unroll
                    for (int mi = 0; mi < 2; mi++) {
#pragma unroll
                        for (int half = 0; half < 2; half++) {
                            int m = wy * 32 + mi * 16 + half * 8 + g;
                            Vs[c * PPITCH + m] = acc[mi][j][half * 2 + 0];
                            Vs[(c + 1) * PPITCH + m] = acc[mi][j][half * 2 + 1];
                        }
                    }
                }
            }
            __syncthreads();
            const int hglob = blockIdx.x * 2 + p;
            // 16 warps: warp-half (wid>>3) picks m segment, (wid&7) picks n rows.
#pragma unroll
            for (int rr = 0; rr < 8; rr++) {
                int n_local = (wid & 7) * 8 + rr;          // 0..63 = hd
                float bv = bias[n0 + p * 64 + n_local];
                int mseg = (wid >> 3) * 128 + lane * 4;    // 0..252
                float4 vv = *(float4*)&Vs[n_local * PPITCH + mseg];
                __half2 h0 = __floats2half2_rn(vv.x + bv, vv.y + bv);
                __half2 h1 = __floats2half2_rn(vv.z + bv, vv.w + bv);
                int m = m0 + mseg;
                int b = m >> 11;
                int s = m & (SS - 1);
                uint2 pk = make_uint2(*(unsigned*)&h0, *(unsigned*)&h1);
                *(uint2*)&dst[((size_t)((b * HH + hglob) * HD) + n_local) * SS + s] = pk;
            }
        }
    } else {
        const float sc = (which == 0) ? QSCALE : 1.0f;
#pragma unroll
        for (int j = 0; j < 8; j++) {
            const int cglob = n0 + wx * 64 + j * 8 + 2 * t;
            const int h = cglob >> 6;
            const int hd = cglob & 63;
            const float b0v = bias[cglob];
            const float b1v = bias[cglob + 1];
#pragma unroll
            for (int mi = 0; mi < 2; mi++) {
#pragma unroll
                for (int half = 0; half < 2; half++) {
                    int r = m0 + wy * 32 + mi * 16 + g + half * 8;
                    int b = r >> 11;
                    int s = r & (SS - 1);
                    __half2 hv = __floats2half2_rn((acc[mi][j][half * 2 + 0] + b0v) * sc,
                                                   (acc[mi][j][half * 2 + 1] + b1v) * sc);
                    *(__half2*)&dst[((size_t)((b * HH + h) * SS) + s) * HD + hd] = hv;
                }
            }
        }
    }
}

// ---------------------------------------------------------------------------
// Flash attention v6 (round-15 proven) + heavy-first q-tile order.
// ---------------------------------------------------------------------------
#define KLD 72
#define KTILE_B (64 * KLD * 2)
#define QS_B 0
#define KS_B (128 * KLD * 2)
#define VS_B (KS_B + 2 * KTILE_B)
#define ATTN_SMEM_BYTES (KS_B + 4 * KTILE_B)

__global__ __launch_bounds__(256, 2) void attn_kernel(
    const float* __restrict__ qin, float* __restrict__ out) {
    const uint32_t sb = smem_u32(dynsmem);

    const int qt = gridDim.x - 1 - blockIdx.x;   // heavy CTAs scheduled first
    const int h  = blockIdx.y;
    const int b  = blockIdx.z;
    const int q0 = qt * 128;
    const int klen = g_klen[b];
    const int qlen = g_qlen[b];

    const int tid = threadIdx.x;
    const int lane = tid & 31;
    const int w = tid >> 5;
    const int g = lane >> 2;
    const int t = lane & 3;

    if (q0 >= qlen) {
#pragma unroll
        for (int i = 0; i < 8; i++) {
            int id = tid + 256 * i;
            int row = id >> 4;
            int cf = (id & 15) * 4;
            size_t oidx = (size_t)(b * SS + q0 + row) * DD + h * HD + cf;
            *(float4*)&out[oidx] = *(const float4*)&qin[oidx];
        }
        return;
    }

    const __half* Qb = g_Q + (size_t)((b * HH + h) * SS) * HD;
    const __half* Kb = g_K + (size_t)((b * HH + h) * SS) * HD;
    const __half* Vb = g_V + (size_t)((b * HH + h) * HD) * SS;

    const int kend = min(klen, q0 + 128);
    const int nt = (kend + 63) >> 6;

    auto load_kv = [&](int ti, int st) {
        const int k0 = ti * 64;
        const uint32_t kbase = sb + KS_B + (uint32_t)st * KTILE_B;
        const uint32_t vbase = sb + VS_B + (uint32_t)st * KTILE_B;
#pragma unroll
        for (int i = 0; i < 2; i++) {
            int id = tid + 256 * i;
            int row = id >> 3;
            int cf = (id & 7) * 8;
            cp16(kbase + (uint32_t)(row * KLD + cf) * 2, Kb + (size_t)(k0 + row) * HD + cf);
            cp16(vbase + (uint32_t)(row * KLD + cf) * 2, Vb + (size_t)row * SS + k0 + cf);
        }
    };

    load_kv(0, 0); CP_COMMIT();

#pragma unroll
    for (int i = 0; i < 4; i++) {
        int id = tid + 256 * i;
        int row = id >> 3;
        int cf = (id & 7) * 8;
        cp16(sb + QS_B + (uint32_t)(row * KLD + cf) * 2, Qb + (size_t)(q0 + row) * HD + cf);
    }
    CP_COMMIT();   // Q gets its own group

    const int qr = q0 + w * 16;

    const int row_sel = lane & 7;
    const int tl = lane >> 3;
    const uint32_t qa_base = sb + QS_B +
        2u * (uint32_t)((w * 16 + (tl & 1) * 8 + row_sel) * KLD + (tl >> 1) * 8);
    const uint32_t bfrag_off =
        2u * (uint32_t)(((tl >> 1) * 8 + row_sel) * KLD + (tl & 1) * 8);
    const uint32_t PSTRIDE = 2u * 16u * KLD;

    float m0r = -INFINITY, m1r = -INFINITY;
    float l0 = 0.0f, l1 = 0.0f;
    float acc[8][4] = {};

    for (int ti = 0; ti < nt; ti++) {
        const int k0 = ti * 64;
        const int st = ti & 1;
        __syncthreads();
        if (ti + 1 < nt) { load_kv(ti + 1, (ti + 1) & 1); CP_COMMIT(); CP_WAIT1(); }
        else CP_WAIT0();
        __syncthreads();

        const uint32_t ks_u = sb + KS_B + (uint32_t)st * KTILE_B;
        const uint32_t vt_u = sb + VS_B + (uint32_t)st * KTILE_B;

        float s[8][4] = {};
#pragma unroll
        for (int kb = 0; kb < 4; kb++) {
            const uint32_t kcb = (uint32_t)(kb * 32);
            unsigned a0, a1, a2, a3;
            ldsm4(a0, a1, a2, a3, qa_base + kcb);
#pragma unroll
            for (int p = 0; p < 4; p++) {
                unsigned b0, b1, b2, b3;
                ldsm4(b0, b1, b2, b3, ks_u + bfrag_off + p * PSTRIDE + kcb);
                mma16(s[2 * p][0], s[2 * p][1], s[2 * p][2], s[2 * p][3],
                      a0, a1, a2, a3, b0, b1);
                mma16(s[2 * p + 1][0], s[2 * p + 1][1], s[2 * p + 1][2], s[2 * p + 1][3],
                      a0, a1, a2, a3, b2, b3);
            }
        }

        const int qq0 = qr + g;
        const int qq1 = qr + 8 + g;
        if (k0 + 63 > qr || k0 + 64 > klen) {
#pragma unroll
            for (int j = 0; j < 8; j++) {
                int c0 = k0 + j * 8 + 2 * t;
                int c1 = c0 + 1;
                if (c0 > qq0 || c0 >= klen) s[j][0] = -INFINITY;
                if (c1 > qq0 || c1 >= klen) s[j][1] = -INFINITY;
                if (c0 > qq1 || c0 >= klen) s[j][2] = -INFINITY;
                if (c1 > qq1 || c1 >= klen) s[j][3] = -INFINITY;
            }
        }

        float mt0 = -INFINITY, mt1 = -INFINITY;
#pragma unroll
        for (int j = 0; j < 8; j++) {
            mt0 = fmaxf(mt0, fmaxf(s[j][0], s[j][1]));
            mt1 = fmaxf(mt1, fmaxf(s[j][2], s[j][3]));
        }
        mt0 = fmaxf(mt0, __shfl_xor_sync(0xffffffffu, mt0, 1));
        mt0 = fmaxf(mt0, __shfl_xor_sync(0xffffffffu, mt0, 2));
        mt1 = fmaxf(mt1, __shfl_xor_sync(0xffffffffu, mt1, 1));
        mt1 = fmaxf(mt1, __shfl_xor_sync(0xffffffffu, mt1, 2));

        float mn0 = fmaxf(m0r, mt0);
        float mn1 = fmaxf(m1r, mt1);
        float alpha0, alpha1, sum0 = 0.0f, sum1 = 0.0f;

        if (mn0 == -INFINITY) {
            alpha0 = 1.0f;
#pragma unroll
            for (int j = 0; j < 8; j++) { s[j][0] = 0.0f; s[j][1] = 0.0f; }
        } else {
            alpha0 = (m0r == -INFINITY) ? 0.0f : exp2f(m0r - mn0);
#pragma unroll
            for (int j = 0; j < 8; j++) {
                s[j][0] = exp2f(s[j][0] - mn0);
                s[j][1] = exp2f(s[j][1] - mn0);
                sum0 += s[j][0] + s[j][1];
            }
        }
        if (mn1 == -INFINITY) {
            alpha1 = 1.0f;
#pragma unroll
            for (int j = 0; j < 8; j++) { s[j][2] = 0.0f; s[j][3] = 0.0f; }
        } else {
            alpha1 = (m1r == -INFINITY) ? 0.0f : exp2f(m1r - mn1);
#pragma unroll
            for (int j = 0; j < 8; j++) {
                s[j][2] = exp2f(s[j][2] - mn1);
                s[j][3] = exp2f(s[j][3] - mn1);
                sum1 += s[j][2] + s[j][3];
            }
        }
        sum0 += __shfl_xor_sync(0xffffffffu, sum0, 1);
        sum0 += __shfl_xor_sync(0xffffffffu, sum0, 2);
        sum1 += __shfl_xor_sync(0xffffffffu, sum1, 1);
        sum1 += __shfl_xor_sync(0xffffffffu, sum1, 2);
        l0 = l0 * alpha0 + sum0;  m0r = mn0;
        l1 = l1 * alpha1 + sum1;  m1r = mn1;

#pragma unroll
        for (int j = 0; j < 8; j++) {
            acc[j][0] *= alpha0; acc[j][1] *= alpha0;
            acc[j][2] *= alpha1; acc[j][3] *= alpha1;
        }

#pragma unroll
        for (int kb = 0; kb < 4; kb++) {
            unsigned a0 = packh2(s[2 * kb][0], s[2 * kb][1]);
            unsigned a1 = packh2(s[2 * kb][2], s[2 * kb][3]);
            unsigned a2 = packh2(s[2 * kb + 1][0], s[2 * kb + 1][1]);
            unsigned a3 = packh2(s[2 * kb + 1][2], s[2 * kb + 1][3]);
            const uint32_t kcb = (uint32_t)(kb * 32);
#pragma unroll
            for (int p = 0; p < 4; p++) {
                unsigned b0, b1, b2, b3;
                ldsm4(b0, b1, b2, b3, vt_u + bfrag_off + p * PSTRIDE + kcb);
                mma16(acc[2 * p][0], acc[2 * p][1], acc[2 * p][2], acc[2 * p][3],
                      a0, a1, a2, a3, b0, b1);
                mma16(acc[2 * p + 1][0], acc[2 * p + 1][1], acc[2 * p + 1][2], acc[2 * p + 1][3],
                      a0, a1, a2, a3, b2, b3);
            }
        }
    }

    float inv0 = (l0 > 0.0f) ? (1.0f / l0) : 0.0f;
    float inv1 = (l1 > 0.0f) ? (1.0f / l1) : 0.0f;
    const int qq0 = qr + g;
    const int qq1 = qr + 8 + g;
#pragma unroll
    for (int j = 0; j < 8; j++) {
        int c = j * 8 + 2 * t;
        {
            size_t oidx = (size_t)(b * SS + qq0) * DD + h * HD + c;
            float2 r2 = *(const float2*)&qin[oidx];
            float2 o = (qq0 >= qlen) ? r2
                     : make_float2(acc[j][0] * inv0 + r2.x, acc[j][1] * inv0 + r2.y);
            *(float2*)&out[oidx] = o;
        }
        {
            size_t oidx = (size_t)(b * SS + qq1) * DD + h * HD + c;
            float2 r2 = *(const float2*)&qin[oidx];
            float2 o = (qq1 >= qlen) ? r2
                     : make_float2(acc[j][2] * inv1 + r2.x, acc[j][3] * inv1 + r2.y);
            *(float2*)&out[oidx] = o;
        }
    }
}

// ---------------------------------------------------------------------------
extern "C" void kernel_launch(void* const* d_in, const int* in_sizes, int n_in,
                              void* d_out, int out_size) {
    const float* q  = (const float*)d_in[0];
    const float* k  = (const float*)d_in[1];
    const float* v  = (const float*)d_in[2];
    const float* Wq = (const float*)d_in[3];
    const float* bq = (const float*)d_in[4];
    const float* Wk = (const float*)d_in[5];
    const float* bk = (const float*)d_in[6];
    const float* Wv = (const float*)d_in[7];
    const float* bv = (const float*)d_in[8];
    const unsigned char* km = (const unsigned char*)d_in[9];
    const unsigned char* qm = (const unsigned char*)d_in[10];
    float* out = (float*)d_out;

    static bool attr_set = false;
    if (!attr_set) {
        cudaFuncSetAttribute(attn_kernel,
                             cudaFuncAttributeMaxDynamicSharedMemorySize,
                             ATTN_SMEM_BYTES);
        cudaFuncSetAttribute(proj_kernel,
                             cudaFuncAttributeMaxDynamicSharedMemorySize,
                             PROJ_SMEM);
        attr_set = true;
    }

    dim3 cg(NX / 8 / 256, 6);
    cvt_kernel<<<cg, 256>>>(q, k, v, Wq, Wk, Wv);

    dim3 pg(DD / 128, (BB * SS) / 256, 3);
    proj_kernel<<<pg, 512, PROJ_SMEM>>>(bq, bk, bv, km, qm);

    dim3 ag(SS / 128, HH, BB);
    attn_kernel<<<ag, 256, ATTN_SMEM_BYTES>>>(q, out);
}